// round 1
// baseline (speedup 1.0000x reference)
#include <cuda_runtime.h>
#include <cstdint>
#include <cstddef>

#define NB 2
#define SL 2048
#define DM 2048
#define NH 16
#define DH 128
#define HIDN 5461
#define BSROWS (NB*SL)

// ---------------- scratch (device globals: allocation-free rule) ----------------
__device__ float g_h [(size_t)BSROWS*DM];
__device__ float g_q [(size_t)BSROWS*DM];
__device__ float g_k [(size_t)BSROWS*DM];
__device__ float g_v [(size_t)BSROWS*DM];
__device__ float g_g [(size_t)BSROWS*DM];
__device__ float g_r [(size_t)BSROWS*DM];
__device__ float g_a [(size_t)BSROWS*DM];
__device__ float g_x1[(size_t)BSROWS*DM];
__device__ float g_h2[(size_t)BSROWS*DM];
__device__ float g_f1[(size_t)BSROWS*HIDN];
__device__ float g_f2[(size_t)BSROWS*HIDN];

// ---------------- helpers ----------------
__device__ __forceinline__ unsigned f2tf(float x) {
    unsigned r;
    asm("cvt.rna.tf32.f32 %0, %1;" : "=r"(r) : "f"(x));
    return r;
}

__device__ __forceinline__ void mma8(float* c, const unsigned* a, const unsigned* b) {
    asm volatile(
        "mma.sync.aligned.m16n8k8.row.col.f32.tf32.tf32.f32 "
        "{%0,%1,%2,%3}, {%4,%5,%6,%7}, {%8,%9}, {%0,%1,%2,%3};\n"
        : "+f"(c[0]), "+f"(c[1]), "+f"(c[2]), "+f"(c[3])
        : "r"(a[0]), "r"(a[1]), "r"(a[2]), "r"(a[3]), "r"(b[0]), "r"(b[1]));
}

// ---------------- LayerNorm: one block per row (D=2048) ----------------
__global__ __launch_bounds__(256)
void ln_kernel(const float* __restrict__ x, const float* __restrict__ w,
               const float* __restrict__ b, float* __restrict__ out)
{
    __shared__ float red[16];
    const int row = blockIdx.x;
    const float* xr = x + (size_t)row * DM;
    float vals[8];
    float s = 0.f, ss = 0.f;
#pragma unroll
    for (int j = 0; j < 8; j++) {
        float v = xr[threadIdx.x + j * 256];
        vals[j] = v; s += v; ss += v * v;
    }
#pragma unroll
    for (int o = 16; o > 0; o >>= 1) {
        s  += __shfl_xor_sync(0xFFFFFFFFu, s,  o);
        ss += __shfl_xor_sync(0xFFFFFFFFu, ss, o);
    }
    const int warp = threadIdx.x >> 5, lane = threadIdx.x & 31;
    if (lane == 0) { red[warp] = s; red[8 + warp] = ss; }
    __syncthreads();
    s = 0.f; ss = 0.f;
#pragma unroll
    for (int k = 0; k < 8; k++) { s += red[k]; ss += red[8 + k]; }
    const float mean = s * (1.f / DM);
    const float var  = ss * (1.f / DM) - mean * mean;
    const float rstd = rsqrtf(var + 1e-5f);
#pragma unroll
    for (int j = 0; j < 8; j++) {
        int col = threadIdx.x + j * 256;
        out[(size_t)row * DM + col] = (vals[j] - mean) * rstd * w[col] + b[col];
    }
}

// ---------------- per-head GroupNorm (128 contiguous floats / group), in place ----------------
__global__ __launch_bounds__(256)
void gn_kernel(float* __restrict__ ret)
{
    const int gi = blockIdx.x * 8 + (threadIdx.x >> 5);
    const int lane = threadIdx.x & 31;
    float4* p = reinterpret_cast<float4*>(ret + (size_t)gi * DH) + lane;
    float4 v = *p;
    float s  = v.x + v.y + v.z + v.w;
    float ss = v.x*v.x + v.y*v.y + v.z*v.z + v.w*v.w;
#pragma unroll
    for (int o = 16; o > 0; o >>= 1) {
        s  += __shfl_xor_sync(0xFFFFFFFFu, s,  o);
        ss += __shfl_xor_sync(0xFFFFFFFFu, ss, o);
    }
    const float mean = s * (1.f / DH);
    const float var  = ss * (1.f / DH) - mean * mean;
    const float rstd = rsqrtf(var + 1e-5f);
    v.x = (v.x - mean) * rstd; v.y = (v.y - mean) * rstd;
    v.z = (v.z - mean) * rstd; v.w = (v.w - mean) * rstd;
    *p = v;
}

// ---------------- silu(a) * b -> out (grid-stride) ----------------
__global__ __launch_bounds__(256)
void gate_kernel(const float* __restrict__ ga, const float* __restrict__ gb,
                 float* __restrict__ out, size_t n)
{
    size_t i = (size_t)blockIdx.x * blockDim.x + threadIdx.x;
    const size_t stride = (size_t)gridDim.x * blockDim.x;
    for (; i < n; i += stride) {
        float x = ga[i];
        out[i] = (x / (1.f + expf(-x))) * gb[i];
    }
}

// ---------------- 3xTF32 GEMM: C = A[MxK] * B[KxN] (+Res), fp32 in/out ----------------
#define TM 128
#define TN 128
#define TK 32
#define GLDA 132
#define GLDB 132
#define GEMM_SMEM ((TK*GLDA*2 + TK*GLDB*2)*4)

__global__ __launch_bounds__(256, 1)
void gemm3_kernel(const float* __restrict__ A, const float* __restrict__ Bm,
                  const float* __restrict__ Res, float* __restrict__ C,
                  int M, int N, int K)
{
    extern __shared__ float smg[];
    float* Ah = smg;
    float* Bh = Ah + TK * GLDA;
    float* Al = Bh + TK * GLDB;
    float* Bl = Al + TK * GLDA;

    const int tid  = threadIdx.x;
    const int lane = tid & 31;
    const int warp = tid >> 5;
    const int gq = lane >> 2;   // 0..7 (group row)
    const int tg = lane & 3;    // 0..3 (thread in group)
    const int wm = warp >> 2;   // 0..1
    const int wn = warp & 3;    // 0..3
    const int bm = blockIdx.y * TM;
    const int bn = blockIdx.x * TN;

    float acc[4][4][4];
#pragma unroll
    for (int a = 0; a < 4; a++)
#pragma unroll
        for (int b = 0; b < 4; b++)
#pragma unroll
            for (int c = 0; c < 4; c++) acc[a][b][c] = 0.f;

    for (int k0 = 0; k0 < K; k0 += TK) {
        // A tile 128x32 -> smem transposed [k][m], hi/lo split
#pragma unroll
        for (int it = 0; it < 16; it++) {
            int idx = tid + it * 256;
            int m = idx >> 5, kk = idx & 31;
            int gm = bm + m, gk = k0 + kk;
            float vv = 0.f;
            if (gm < M && gk < K) vv = __ldg(&A[(size_t)gm * K + gk]);
            float hi = __uint_as_float(f2tf(vv));
            Ah[kk * GLDA + m] = hi;
            Al[kk * GLDA + m] = __uint_as_float(f2tf(vv - hi));
        }
        // B tile 32x128 -> smem [k][n], hi/lo split
#pragma unroll
        for (int it = 0; it < 16; it++) {
            int idx = tid + it * 256;
            int kk = idx >> 7, n = idx & 127;
            int gk = k0 + kk, gn = bn + n;
            float vv = 0.f;
            if (gk < K && gn < N) vv = __ldg(&Bm[(size_t)gk * N + gn]);
            float hi = __uint_as_float(f2tf(vv));
            Bh[kk * GLDB + n] = hi;
            Bl[kk * GLDB + n] = __uint_as_float(f2tf(vv - hi));
        }
        __syncthreads();
#pragma unroll
        for (int ks = 0; ks < 4; ks++) {
            const int kb = ks * 8;
            unsigned ah[4][4], al[4][4], bhf[4][2], blf[4][2];
#pragma unroll
            for (int mt = 0; mt < 4; mt++) {
                int m = wm * 64 + mt * 16 + gq;
                int r0 = (kb + tg) * GLDA + m;
                int r1 = (kb + tg + 4) * GLDA + m;
                ah[mt][0] = __float_as_uint(Ah[r0]);
                ah[mt][1] = __float_as_uint(Ah[r0 + 8]);
                ah[mt][2] = __float_as_uint(Ah[r1]);
                ah[mt][3] = __float_as_uint(Ah[r1 + 8]);
                al[mt][0] = __float_as_uint(Al[r0]);
                al[mt][1] = __float_as_uint(Al[r0 + 8]);
                al[mt][2] = __float_as_uint(Al[r1]);
                al[mt][3] = __float_as_uint(Al[r1 + 8]);
            }
#pragma unroll
            for (int nt = 0; nt < 4; nt++) {
                int n = wn * 32 + nt * 8 + gq;
                bhf[nt][0] = __float_as_uint(Bh[(kb + tg) * GLDB + n]);
                bhf[nt][1] = __float_as_uint(Bh[(kb + tg + 4) * GLDB + n]);
                blf[nt][0] = __float_as_uint(Bl[(kb + tg) * GLDB + n]);
                blf[nt][1] = __float_as_uint(Bl[(kb + tg + 4) * GLDB + n]);
            }
#pragma unroll
            for (int mt = 0; mt < 4; mt++)
#pragma unroll
                for (int nt = 0; nt < 4; nt++) {
                    mma8(acc[mt][nt], ah[mt], bhf[nt]);
                    mma8(acc[mt][nt], ah[mt], blf[nt]);
                    mma8(acc[mt][nt], al[mt], bhf[nt]);
                }
        }
        __syncthreads();
    }

#pragma unroll
    for (int mt = 0; mt < 4; mt++)
#pragma unroll
        for (int nt = 0; nt < 4; nt++) {
            int r0 = bm + wm * 64 + mt * 16 + gq;
            int c0 = bn + wn * 32 + nt * 8 + tg * 2;
#pragma unroll
            for (int e = 0; e < 4; e++) {
                int r = r0 + (e >> 1) * 8;
                int c = c0 + (e & 1);
                if (r < M && c < N) {
                    float vv = acc[mt][nt][e];
                    if (Res) vv += Res[(size_t)r * N + c];
                    C[(size_t)r * N + c] = vv;
                }
            }
        }
}

// ---------------- Retention: flash-style masked attention (no softmax) ----------------
// grid = (S/64, B*H); block 256. O written in [B,S,D] layout (head-major columns).
#define RET_SMEM ((64*132*2 + 64*136 + 64*68 + 128)*4)

__global__ __launch_bounds__(256, 1)
void retention_kernel(const float* __restrict__ Q, const float* __restrict__ Kt,
                      const float* __restrict__ V, float* __restrict__ O)
{
    extern __shared__ float smr[];
    float* Qs = smr;              // [64][132]
    float* Ks = Qs + 64 * 132;    // [64][132]
    float* Vs = Ks + 64 * 132;    // [64][136]
    float* Ss = Vs + 64 * 136;    // [64][68]
    float* dp = Ss + 64 * 68;     // [128]

    const int tid  = threadIdx.x;
    const int lane = tid & 31;
    const int warp = tid >> 5;
    const int gq = lane >> 2;
    const int tg = lane & 3;
    const int wm = warp >> 2;     // 0..1 over 64 q-rows
    const int wn = warp & 3;      // 0..3
    const int bh = blockIdx.y;
    const int b = bh >> 4, h = bh & 15;
    const int qb = blockIdx.x * 64;

    const float gamma = 1.f - exp2f(-5.f - (float)h);
    const float lg = log2f(gamma);
    const size_t rowbase = (size_t)(b * SL) * DM + (size_t)h * DH;

    // Q tile (tf32-rounded)
#pragma unroll
    for (int it = 0; it < 32; it++) {
        int idx = tid + it * 256;
        int r = idx >> 7, d = idx & 127;
        Qs[r * 132 + d] = __uint_as_float(f2tf(Q[rowbase + (size_t)(qb + r) * DM + d]));
    }

    float acco[2][4][4];
#pragma unroll
    for (int a = 0; a < 2; a++)
#pragma unroll
        for (int bq = 0; bq < 4; bq++)
#pragma unroll
            for (int c = 0; c < 4; c++) acco[a][bq][c] = 0.f;

    for (int kt = 0; kt <= blockIdx.x; kt++) {
        const int kb = kt * 64;
        __syncthreads();  // prior iteration readers of Ks/Vs/Ss done; also orders Qs writes
#pragma unroll
        for (int it = 0; it < 32; it++) {
            int idx = tid + it * 256;
            int r = idx >> 7, d = idx & 127;
            size_t gidx = rowbase + (size_t)(kb + r) * DM + d;
            Ks[r * 132 + d] = __uint_as_float(f2tf(Kt[gidx]));
            Vs[r * 136 + d] = __uint_as_float(f2tf(V[gidx]));
        }
        if (tid < 128) {
            int e = (qb - kb) - 63 + tid;   // global decay exponent s-t for index tid
            dp[tid] = (e < 0) ? 0.f : 0.08838834764831845f * exp2f((float)e * lg);
        }
        __syncthreads();

        // S[64q x 64t] = Qs @ Ks^T over dh=128 (warp tile 32x16)
        float accs[2][2][4];
#pragma unroll
        for (int a = 0; a < 2; a++)
#pragma unroll
            for (int bq = 0; bq < 2; bq++)
#pragma unroll
                for (int c = 0; c < 4; c++) accs[a][bq][c] = 0.f;
#pragma unroll
        for (int ks = 0; ks < 16; ks++) {
            const int kkk = ks * 8;
            unsigned af[2][4], bf[2][2];
#pragma unroll
            for (int mt = 0; mt < 2; mt++) {
                int m = wm * 32 + mt * 16 + gq;
                af[mt][0] = __float_as_uint(Qs[m * 132 + kkk + tg]);
                af[mt][1] = __float_as_uint(Qs[(m + 8) * 132 + kkk + tg]);
                af[mt][2] = __float_as_uint(Qs[m * 132 + kkk + tg + 4]);
                af[mt][3] = __float_as_uint(Qs[(m + 8) * 132 + kkk + tg + 4]);
            }
#pragma unroll
            for (int nt = 0; nt < 2; nt++) {
                int n = wn * 16 + nt * 8 + gq;
                bf[nt][0] = __float_as_uint(Ks[n * 132 + kkk + tg]);
                bf[nt][1] = __float_as_uint(Ks[n * 132 + kkk + tg + 4]);
            }
#pragma unroll
            for (int mt = 0; mt < 2; mt++)
#pragma unroll
                for (int nt = 0; nt < 2; nt++)
                    mma8(accs[mt][nt], af[mt], bf[nt]);
        }
        // apply decay (+ dh^-0.5 scale + exact causal mask) and stage S into smem
#pragma unroll
        for (int mt = 0; mt < 2; mt++)
#pragma unroll
            for (int nt = 0; nt < 2; nt++) {
                int sr0 = wm * 32 + mt * 16 + gq;
                int tc0 = wn * 16 + nt * 8 + tg * 2;
#pragma unroll
                for (int e = 0; e < 4; e++) {
                    int sr = sr0 + (e >> 1) * 8;
                    int tc = tc0 + (e & 1);
                    float coeff = dp[sr - tc + 63];
                    Ss[sr * 68 + tc] = __uint_as_float(f2tf(accs[mt][nt][e] * coeff));
                }
            }
        __syncthreads();

        // O[64 x 128] += Ss[64x64] @ Vs[64x128] (warp tile 32x32)
#pragma unroll
        for (int ks = 0; ks < 8; ks++) {
            const int kkk = ks * 8;
            unsigned af[2][4], bf[4][2];
#pragma unroll
            for (int mt = 0; mt < 2; mt++) {
                int m = wm * 32 + mt * 16 + gq;
                af[mt][0] = __float_as_uint(Ss[m * 68 + kkk + tg]);
                af[mt][1] = __float_as_uint(Ss[(m + 8) * 68 + kkk + tg]);
                af[mt][2] = __float_as_uint(Ss[m * 68 + kkk + tg + 4]);
                af[mt][3] = __float_as_uint(Ss[(m + 8) * 68 + kkk + tg + 4]);
            }
#pragma unroll
            for (int nt = 0; nt < 4; nt++) {
                int n = wn * 32 + nt * 8 + gq;
                bf[nt][0] = __float_as_uint(Vs[(kkk + tg) * 136 + n]);
                bf[nt][1] = __float_as_uint(Vs[(kkk + tg + 4) * 136 + n]);
            }
#pragma unroll
            for (int mt = 0; mt < 2; mt++)
#pragma unroll
                for (int nt = 0; nt < 4; nt++)
                    mma8(acco[mt][nt], af[mt], bf[nt]);
        }
    }

    // epilogue: write to [B,S,D] layout
#pragma unroll
    for (int mt = 0; mt < 2; mt++)
#pragma unroll
        for (int nt = 0; nt < 4; nt++) {
            int r0 = qb + wm * 32 + mt * 16 + gq;
            int c0 = wn * 32 + nt * 8 + tg * 2;
#pragma unroll
            for (int e = 0; e < 4; e++) {
                int r = r0 + (e >> 1) * 8;
                int c = c0 + (e & 1);
                O[rowbase + (size_t)r * DM + c] = acco[mt][nt][e];
            }
        }
}

// ---------------- launch ----------------
extern "C" void kernel_launch(void* const* d_in, const int* in_sizes, int n_in,
                              void* d_out, int out_size)
{
    const float* x   = (const float*)d_in[0];
    const float* n1w = (const float*)d_in[1];
    const float* n1b = (const float*)d_in[2];
    const float* wq  = (const float*)d_in[3];
    const float* wk  = (const float*)d_in[4];
    const float* wv  = (const float*)d_in[5];
    const float* wg  = (const float*)d_in[6];
    const float* wo  = (const float*)d_in[7];
    const float* n2w = (const float*)d_in[8];
    const float* n2b = (const float*)d_in[9];
    const float* w1  = (const float*)d_in[10];
    const float* w2  = (const float*)d_in[11];
    const float* w3  = (const float*)d_in[12];
    float* out = (float*)d_out;

    float *h, *q, *k, *v, *g, *r, *a, *x1, *h2, *f1, *f2;
    cudaGetSymbolAddress((void**)&h,  g_h);
    cudaGetSymbolAddress((void**)&q,  g_q);
    cudaGetSymbolAddress((void**)&k,  g_k);
    cudaGetSymbolAddress((void**)&v,  g_v);
    cudaGetSymbolAddress((void**)&g,  g_g);
    cudaGetSymbolAddress((void**)&r,  g_r);
    cudaGetSymbolAddress((void**)&a,  g_a);
    cudaGetSymbolAddress((void**)&x1, g_x1);
    cudaGetSymbolAddress((void**)&h2, g_h2);
    cudaGetSymbolAddress((void**)&f1, g_f1);
    cudaGetSymbolAddress((void**)&f2, g_f2);

    cudaFuncSetAttribute((const void*)gemm3_kernel,
                         cudaFuncAttributeMaxDynamicSharedMemorySize, GEMM_SMEM);
    cudaFuncSetAttribute((const void*)retention_kernel,
                         cudaFuncAttributeMaxDynamicSharedMemorySize, RET_SMEM);

    const dim3 gproj(DM / TN, BSROWS / TM);             // (16, 32)
    const dim3 gffn((HIDN + TN - 1) / TN, BSROWS / TM); // (43, 32)

    // x -> LN1 -> h
    ln_kernel<<<BSROWS, 256>>>(x, n1w, n1b, h);
    // projections
    gemm3_kernel<<<gproj, 256, GEMM_SMEM>>>(h, wq, nullptr, q, BSROWS, DM, DM);
    gemm3_kernel<<<gproj, 256, GEMM_SMEM>>>(h, wk, nullptr, k, BSROWS, DM, DM);
    gemm3_kernel<<<gproj, 256, GEMM_SMEM>>>(h, wv, nullptr, v, BSROWS, DM, DM);
    gemm3_kernel<<<gproj, 256, GEMM_SMEM>>>(h, wg, nullptr, g, BSROWS, DM, DM);
    // retention + per-head groupnorm
    retention_kernel<<<dim3(SL / 64, NB * NH), 256, RET_SMEM>>>(q, k, v, r);
    gn_kernel<<<(BSROWS * NH) / 8, 256>>>(r);
    // swish gate, output projection with residual
    gate_kernel<<<4096, 256>>>(g, r, a, (size_t)BSROWS * DM);
    gemm3_kernel<<<gproj, 256, GEMM_SMEM>>>(a, wo, x, x1, BSROWS, DM, DM);
    // FFN
    ln_kernel<<<BSROWS, 256>>>(x1, n2w, n2b, h2);
    gemm3_kernel<<<gffn, 256, GEMM_SMEM>>>(h2, w1, nullptr, f1, BSROWS, HIDN, DM);
    gemm3_kernel<<<gffn, 256, GEMM_SMEM>>>(h2, w2, nullptr, f2, BSROWS, HIDN, DM);
    gate_kernel<<<4096, 256>>>(f1, f2, f1, (size_t)BSROWS * HIDN);
    gemm3_kernel<<<gproj, 256, GEMM_SMEM>>>(f1, w3, x1, out, BSROWS, DM, HIDN);
}

// round 2
// speedup vs baseline: 2.2910x; 2.2910x over previous
#include <cuda_runtime.h>
#include <cuda_bf16.h>
#include <cstdint>
#include <cstddef>

#define NB 2
#define SL 2048
#define DM 2048
#define NH 16
#define DH 128
#define HIDN 5461
#define HIDP 5504           // padded to multiple of 128
#define BSROWS (NB*SL)      // 4096

typedef __nv_bfloat16 bf16;

// ---------------- scratch (device globals: allocation-free rule) ----------------
__device__ float g_q [(size_t)BSROWS*DM];
__device__ float g_k [(size_t)BSROWS*DM];
__device__ float g_v [(size_t)BSROWS*DM];
__device__ float g_g [(size_t)BSROWS*DM];
__device__ float g_r [(size_t)BSROWS*DM];
__device__ float g_x1[(size_t)BSROWS*DM];
__device__ float g_f1[(size_t)BSROWS*HIDP];
__device__ float g_f2[(size_t)BSROWS*HIDP];

__device__ bf16 g_h_hi [(size_t)BSROWS*DM];
__device__ bf16 g_h_lo [(size_t)BSROWS*DM];
__device__ bf16 g_h2_hi[(size_t)BSROWS*DM];
__device__ bf16 g_h2_lo[(size_t)BSROWS*DM];
__device__ bf16 g_a_hi [(size_t)BSROWS*DM];
__device__ bf16 g_a_lo [(size_t)BSROWS*DM];
__device__ bf16 g_fg_hi[(size_t)BSROWS*HIDP];
__device__ bf16 g_fg_lo[(size_t)BSROWS*HIDP];

__device__ bf16 g_wq_hi[(size_t)DM*DM], g_wq_lo[(size_t)DM*DM];
__device__ bf16 g_wk_hi[(size_t)DM*DM], g_wk_lo[(size_t)DM*DM];
__device__ bf16 g_wv_hi[(size_t)DM*DM], g_wv_lo[(size_t)DM*DM];
__device__ bf16 g_wg_hi[(size_t)DM*DM], g_wg_lo[(size_t)DM*DM];
__device__ bf16 g_wo_hi[(size_t)DM*DM], g_wo_lo[(size_t)DM*DM];
__device__ bf16 g_w1_hi[(size_t)DM*HIDP], g_w1_lo[(size_t)DM*HIDP];
__device__ bf16 g_w2_hi[(size_t)DM*HIDP], g_w2_lo[(size_t)DM*HIDP];
__device__ bf16 g_w3_hi[(size_t)HIDP*DM], g_w3_lo[(size_t)HIDP*DM];

// ---------------- helpers ----------------
__device__ __forceinline__ unsigned f2tf(float x) {
    unsigned r;
    asm("cvt.rna.tf32.f32 %0, %1;" : "=r"(r) : "f"(x));
    return r;
}

__device__ __forceinline__ void split_bf16(float x, bf16& hi, bf16& lo) {
    hi = __float2bfloat16(x);
    lo = __float2bfloat16(x - __bfloat162float(hi));
}

__device__ __forceinline__ void mma8(float* c, const unsigned* a, const unsigned* b) {
    asm volatile(
        "mma.sync.aligned.m16n8k8.row.col.f32.tf32.tf32.f32 "
        "{%0,%1,%2,%3}, {%4,%5,%6,%7}, {%8,%9}, {%0,%1,%2,%3};\n"
        : "+f"(c[0]), "+f"(c[1]), "+f"(c[2]), "+f"(c[3])
        : "r"(a[0]), "r"(a[1]), "r"(a[2]), "r"(a[3]), "r"(b[0]), "r"(b[1]));
}

__device__ __forceinline__ void mma16(float* c, const unsigned* a, const unsigned* b) {
    asm volatile(
        "mma.sync.aligned.m16n8k16.row.col.f32.bf16.bf16.f32 "
        "{%0,%1,%2,%3}, {%4,%5,%6,%7}, {%8,%9}, {%0,%1,%2,%3};\n"
        : "+f"(c[0]), "+f"(c[1]), "+f"(c[2]), "+f"(c[3])
        : "r"(a[0]), "r"(a[1]), "r"(a[2]), "r"(a[3]), "r"(b[0]), "r"(b[1]));
}

__device__ __forceinline__ void ldsm4(unsigned* r, unsigned addr) {
    asm volatile("ldmatrix.sync.aligned.m8n8.x4.shared.b16 {%0,%1,%2,%3}, [%4];\n"
        : "=r"(r[0]), "=r"(r[1]), "=r"(r[2]), "=r"(r[3]) : "r"(addr));
}
__device__ __forceinline__ void ldsm4t(unsigned* r, unsigned addr) {
    asm volatile("ldmatrix.sync.aligned.m8n8.x4.trans.shared.b16 {%0,%1,%2,%3}, [%4];\n"
        : "=r"(r[0]), "=r"(r[1]), "=r"(r[2]), "=r"(r[3]) : "r"(addr));
}
__device__ __forceinline__ void cpa16(unsigned dst, const void* src) {
    asm volatile("cp.async.cg.shared.global [%0], [%1], 16;\n" :: "r"(dst), "l"(src));
}

// ---------------- elementwise converters ----------------
__global__ __launch_bounds__(256)
void conv_split(const float* __restrict__ src, bf16* __restrict__ hi,
                bf16* __restrict__ lo, size_t n)
{
    size_t i = (size_t)blockIdx.x * 256 + threadIdx.x;
    const size_t st = (size_t)gridDim.x * 256;
    for (; i < n; i += st) { split_bf16(src[i], hi[i], lo[i]); }
}

__global__ __launch_bounds__(256)
void conv_pad_cols(const float* __restrict__ src, bf16* __restrict__ hi,
                   bf16* __restrict__ lo, int rows, int scols, int dcols)
{
    size_t n = (size_t)rows * dcols;
    size_t i = (size_t)blockIdx.x * 256 + threadIdx.x;
    const size_t st = (size_t)gridDim.x * 256;
    for (; i < n; i += st) {
        int r = (int)(i / dcols), c = (int)(i % dcols);
        float v = (c < scols) ? src[(size_t)r * scols + c] : 0.f;
        split_bf16(v, hi[i], lo[i]);
    }
}

__global__ __launch_bounds__(256)
void conv_pad_rows(const float* __restrict__ src, bf16* __restrict__ hi,
                   bf16* __restrict__ lo, int srows, int drows, int cols)
{
    size_t n = (size_t)drows * cols;
    size_t i = (size_t)blockIdx.x * 256 + threadIdx.x;
    const size_t st = (size_t)gridDim.x * 256;
    for (; i < n; i += st) {
        int r = (int)(i / cols);
        float v = (r < srows) ? src[i] : 0.f;
        split_bf16(v, hi[i], lo[i]);
    }
}

// ---------------- LayerNorm -> bf16 hi/lo ----------------
__global__ __launch_bounds__(256)
void ln_kernel(const float* __restrict__ x, const float* __restrict__ w,
               const float* __restrict__ b, bf16* __restrict__ ohi,
               bf16* __restrict__ olo)
{
    __shared__ float red[16];
    const int row = blockIdx.x;
    const float* xr = x + (size_t)row * DM;
    float vals[8];
    float s = 0.f, ss = 0.f;
#pragma unroll
    for (int j = 0; j < 8; j++) {
        float v = xr[threadIdx.x + j * 256];
        vals[j] = v; s += v; ss += v * v;
    }
#pragma unroll
    for (int o = 16; o > 0; o >>= 1) {
        s  += __shfl_xor_sync(0xFFFFFFFFu, s,  o);
        ss += __shfl_xor_sync(0xFFFFFFFFu, ss, o);
    }
    const int warp = threadIdx.x >> 5, lane = threadIdx.x & 31;
    if (lane == 0) { red[warp] = s; red[8 + warp] = ss; }
    __syncthreads();
    s = 0.f; ss = 0.f;
#pragma unroll
    for (int k = 0; k < 8; k++) { s += red[k]; ss += red[8 + k]; }
    const float mean = s * (1.f / DM);
    const float var  = ss * (1.f / DM) - mean * mean;
    const float rstd = rsqrtf(var + 1e-5f);
#pragma unroll
    for (int j = 0; j < 8; j++) {
        int col = threadIdx.x + j * 256;
        float o = (vals[j] - mean) * rstd * w[col] + b[col];
        split_bf16(o, ohi[(size_t)row * DM + col], olo[(size_t)row * DM + col]);
    }
}

// ---------------- per-head GroupNorm in place ----------------
__global__ __launch_bounds__(256)
void gn_kernel(float* __restrict__ ret)
{
    const int gi = blockIdx.x * 8 + (threadIdx.x >> 5);
    const int lane = threadIdx.x & 31;
    float4* p = reinterpret_cast<float4*>(ret + (size_t)gi * DH) + lane;
    float4 v = *p;
    float s  = v.x + v.y + v.z + v.w;
    float ss = v.x*v.x + v.y*v.y + v.z*v.z + v.w*v.w;
#pragma unroll
    for (int o = 16; o > 0; o >>= 1) {
        s  += __shfl_xor_sync(0xFFFFFFFFu, s,  o);
        ss += __shfl_xor_sync(0xFFFFFFFFu, ss, o);
    }
    const float mean = s * (1.f / DH);
    const float var  = ss * (1.f / DH) - mean * mean;
    const float rstd = rsqrtf(var + 1e-5f);
    v.x = (v.x - mean) * rstd; v.y = (v.y - mean) * rstd;
    v.z = (v.z - mean) * rstd; v.w = (v.w - mean) * rstd;
    *p = v;
}

// ---------------- silu(a) * b -> bf16 hi/lo ----------------
__global__ __launch_bounds__(256)
void gate_split(const float* __restrict__ ga, const float* __restrict__ gb,
                bf16* __restrict__ hi, bf16* __restrict__ lo, size_t n)
{
    size_t i = (size_t)blockIdx.x * 256 + threadIdx.x;
    const size_t st = (size_t)gridDim.x * 256;
    for (; i < n; i += st) {
        float x = ga[i];
        float v = (x / (1.f + expf(-x))) * gb[i];
        split_bf16(v, hi[i], lo[i]);
    }
}

// ---------------- bf16x3 GEMM: C = A*B (+Res), ldmatrix + cp.async double buffer ----
// A: [M][K] bf16 hi/lo, B: [K][N] bf16 hi/lo, C/Res fp32 [M][N]. M%128==0, N%128==0, K%32==0.
#define A_BUFB 10240u   // 128 rows * 80B
#define B_BUFB 8704u    // 32 rows * 272B
#define GEMM_SMEM (4*A_BUFB + 4*B_BUFB)   // 75776 B

__device__ __forceinline__ void gemm_prefetch(
    const bf16* __restrict__ Ahi, const bf16* __restrict__ Alo,
    const bf16* __restrict__ Bhi, const bf16* __restrict__ Blo,
    unsigned sA, unsigned sB, int buf, int bm, int bn, int k0, int K, int N, int tid)
{
#pragma unroll
    for (int i = 0; i < 2; i++) {
        int c = tid + i * 256;
        int row = c >> 2, chn = c & 3;
        size_t go = (size_t)(bm + row) * K + k0 + chn * 8;
        unsigned so = (unsigned)buf * A_BUFB + row * 80u + chn * 16u;
        cpa16(sA + so, Ahi + go);
        cpa16(sA + 2u * A_BUFB + so, Alo + go);
    }
#pragma unroll
    for (int i = 0; i < 2; i++) {
        int c = tid + i * 256;
        int row = c >> 4, chn = c & 15;
        size_t go = (size_t)(k0 + row) * N + bn + chn * 8;
        unsigned so = (unsigned)buf * B_BUFB + row * 272u + chn * 16u;
        cpa16(sB + so, Bhi + go);
        cpa16(sB + 2u * B_BUFB + so, Blo + go);
    }
}

__global__ __launch_bounds__(256, 1)
void gemm_bf16x3(const bf16* __restrict__ Ahi, const bf16* __restrict__ Alo,
                 const bf16* __restrict__ Bhi, const bf16* __restrict__ Blo,
                 const float* __restrict__ Res, float* __restrict__ C,
                 int M, int N, int K)
{
    extern __shared__ __align__(16) char smemraw[];
    const unsigned sA = (unsigned)__cvta_generic_to_shared(smemraw);
    const unsigned sB = sA + 4u * A_BUFB;

    const int tid  = threadIdx.x;
    const int lane = tid & 31;
    const int warp = tid >> 5;
    const int wm = warp >> 2;     // 0..1
    const int wn = warp & 3;      // 0..3
    const int bm = blockIdx.y * 128;
    const int bn = blockIdx.x * 128;

    // per-lane ldmatrix offsets (bytes)
    const unsigned laneA = (unsigned)(((lane & 7) + ((lane >> 3) & 1) * 8) * 80 + (lane >> 4) * 16);
    const unsigned laneB = (unsigned)(((lane & 7) + ((lane >> 3) & 1) * 8) * 272 + (lane >> 4) * 16);

    float acc[4][4][4];
#pragma unroll
    for (int a = 0; a < 4; a++)
#pragma unroll
        for (int b = 0; b < 4; b++)
#pragma unroll
            for (int c = 0; c < 4; c++) acc[a][b][c] = 0.f;

    const int nk = K >> 5;
    gemm_prefetch(Ahi, Alo, Bhi, Blo, sA, sB, 0, bm, bn, 0, K, N, tid);
    asm volatile("cp.async.commit_group;\n" ::: "memory");

    for (int t = 0; t < nk; t++) {
        if (t + 1 < nk) {
            gemm_prefetch(Ahi, Alo, Bhi, Blo, sA, sB, (t + 1) & 1, bm, bn, (t + 1) * 32, K, N, tid);
            asm volatile("cp.async.commit_group;\n" ::: "memory");
            asm volatile("cp.async.wait_group 1;\n" ::: "memory");
        } else {
            asm volatile("cp.async.wait_group 0;\n" ::: "memory");
        }
        __syncthreads();

        const int buf = t & 1;
        const unsigned aBase = sA + (unsigned)buf * A_BUFB + (unsigned)(wm * 64 * 80) + laneA;
        const unsigned bBase = sB + (unsigned)buf * B_BUFB + (unsigned)(wn * 32 * 2) + laneB;

#pragma unroll
        for (int ks = 0; ks < 2; ks++) {
            unsigned ah[4][4], al[4][4], bh[2][4], bl[2][4];
#pragma unroll
            for (int mt = 0; mt < 4; mt++) {
                unsigned ad = aBase + (unsigned)(mt * 16 * 80 + ks * 32);
                ldsm4(ah[mt], ad);
                ldsm4(al[mt], ad + 2u * A_BUFB);
            }
#pragma unroll
            for (int p = 0; p < 2; p++) {
                unsigned bd = bBase + (unsigned)(ks * 16 * 272 + p * 32);
                ldsm4t(bh[p], bd);
                ldsm4t(bl[p], bd + 2u * B_BUFB);
            }
#pragma unroll
            for (int mt = 0; mt < 4; mt++)
#pragma unroll
                for (int p = 0; p < 2; p++) {
                    mma16(acc[mt][2*p],   ah[mt], bh[p]);
                    mma16(acc[mt][2*p],   ah[mt], bl[p]);
                    mma16(acc[mt][2*p],   al[mt], bh[p]);
                    mma16(acc[mt][2*p+1], ah[mt], bh[p] + 2);
                    mma16(acc[mt][2*p+1], ah[mt], bl[p] + 2);
                    mma16(acc[mt][2*p+1], al[mt], bh[p] + 2);
                }
        }
        __syncthreads();
    }

    // epilogue (no bounds checks: dims padded)
#pragma unroll
    for (int mt = 0; mt < 4; mt++)
#pragma unroll
        for (int nt = 0; nt < 4; nt++) {
            int r0 = bm + wm * 64 + mt * 16 + (lane >> 2);
            int c0 = bn + wn * 32 + nt * 8 + (lane & 3) * 2;
#pragma unroll
            for (int half = 0; half < 2; half++) {
                int r = r0 + half * 8;
                float2 v = make_float2(acc[mt][nt][half * 2], acc[mt][nt][half * 2 + 1]);
                if (Res) {
                    float2 rv = *reinterpret_cast<const float2*>(&Res[(size_t)r * N + c0]);
                    v.x += rv.x; v.y += rv.y;
                }
                *reinterpret_cast<float2*>(&C[(size_t)r * N + c0]) = v;
            }
        }
}

// ---------------- Retention: flash-style masked attention (tf32) ----------------
#define RET_SMEM ((64*132*2 + 64*136 + 64*68 + 128)*4)

__global__ __launch_bounds__(256, 1)
void retention_kernel(const float* __restrict__ Q, const float* __restrict__ Kt,
                      const float* __restrict__ V, float* __restrict__ O)
{
    extern __shared__ float smr[];
    float* Qs = smr;              // [64][132]
    float* Ks = Qs + 64 * 132;    // [64][132]
    float* Vs = Ks + 64 * 132;    // [64][136]
    float* Ss = Vs + 64 * 136;    // [64][68]
    float* dp = Ss + 64 * 68;     // [128]

    const int tid  = threadIdx.x;
    const int lane = tid & 31;
    const int warp = tid >> 5;
    const int gq = lane >> 2;
    const int tg = lane & 3;
    const int wm = warp >> 2;
    const int wn = warp & 3;
    const int bh = blockIdx.y;
    const int b = bh >> 4, h = bh & 15;
    const int qb = blockIdx.x * 64;

    const float gamma = 1.f - exp2f(-5.f - (float)h);
    const float lg = log2f(gamma);
    const size_t rowbase = (size_t)(b * SL) * DM + (size_t)h * DH;

#pragma unroll
    for (int it = 0; it < 32; it++) {
        int idx = tid + it * 256;
        int r = idx >> 7, d = idx & 127;
        Qs[r * 132 + d] = __uint_as_float(f2tf(Q[rowbase + (size_t)(qb + r) * DM + d]));
    }

    float acco[2][4][4];
#pragma unroll
    for (int a = 0; a < 2; a++)
#pragma unroll
        for (int bq = 0; bq < 4; bq++)
#pragma unroll
            for (int c = 0; c < 4; c++) acco[a][bq][c] = 0.f;

    for (int kt = 0; kt <= blockIdx.x; kt++) {
        const int kb = kt * 64;
        __syncthreads();
#pragma unroll
        for (int it = 0; it < 32; it++) {
            int idx = tid + it * 256;
            int r = idx >> 7, d = idx & 127;
            size_t gidx = rowbase + (size_t)(kb + r) * DM + d;
            Ks[r * 132 + d] = __uint_as_float(f2tf(Kt[gidx]));
            Vs[r * 136 + d] = __uint_as_float(f2tf(V[gidx]));
        }
        if (tid < 128) {
            int e = (qb - kb) - 63 + tid;
            dp[tid] = (e < 0) ? 0.f : 0.08838834764831845f * exp2f((float)e * lg);
        }
        __syncthreads();

        float accs[2][2][4];
#pragma unroll
        for (int a = 0; a < 2; a++)
#pragma unroll
            for (int bq = 0; bq < 2; bq++)
#pragma unroll
                for (int c = 0; c < 4; c++) accs[a][bq][c] = 0.f;
#pragma unroll
        for (int ks = 0; ks < 16; ks++) {
            const int kkk = ks * 8;
            unsigned af[2][4], bf[2][2];
#pragma unroll
            for (int mt = 0; mt < 2; mt++) {
                int m = wm * 32 + mt * 16 + gq;
                af[mt][0] = __float_as_uint(Qs[m * 132 + kkk + tg]);
                af[mt][1] = __float_as_uint(Qs[(m + 8) * 132 + kkk + tg]);
                af[mt][2] = __float_as_uint(Qs[m * 132 + kkk + tg + 4]);
                af[mt][3] = __float_as_uint(Qs[(m + 8) * 132 + kkk + tg + 4]);
            }
#pragma unroll
            for (int nt = 0; nt < 2; nt++) {
                int n = wn * 16 + nt * 8 + gq;
                bf[nt][0] = __float_as_uint(Ks[n * 132 + kkk + tg]);
                bf[nt][1] = __float_as_uint(Ks[n * 132 + kkk + tg + 4]);
            }
#pragma unroll
            for (int mt = 0; mt < 2; mt++)
#pragma unroll
                for (int nt = 0; nt < 2; nt++)
                    mma8(accs[mt][nt], af[mt], bf[nt]);
        }
#pragma unroll
        for (int mt = 0; mt < 2; mt++)
#pragma unroll
            for (int nt = 0; nt < 2; nt++) {
                int sr0 = wm * 32 + mt * 16 + gq;
                int tc0 = wn * 16 + nt * 8 + tg * 2;
#pragma unroll
                for (int e = 0; e < 4; e++) {
                    int sr = sr0 + (e >> 1) * 8;
                    int tc = tc0 + (e & 1);
                    float coeff = dp[sr - tc + 63];
                    Ss[sr * 68 + tc] = __uint_as_float(f2tf(accs[mt][nt][e] * coeff));
                }
            }
        __syncthreads();

#pragma unroll
        for (int ks = 0; ks < 8; ks++) {
            const int kkk = ks * 8;
            unsigned af[2][4], bf[4][2];
#pragma unroll
            for (int mt = 0; mt < 2; mt++) {
                int m = wm * 32 + mt * 16 + gq;
                af[mt][0] = __float_as_uint(Ss[m * 68 + kkk + tg]);
                af[mt][1] = __float_as_uint(Ss[(m + 8) * 68 + kkk + tg]);
                af[mt][2] = __float_as_uint(Ss[m * 68 + kkk + tg + 4]);
                af[mt][3] = __float_as_uint(Ss[(m + 8) * 68 + kkk + tg + 4]);
            }
#pragma unroll
            for (int nt = 0; nt < 4; nt++) {
                int n = wn * 32 + nt * 8 + gq;
                bf[nt][0] = __float_as_uint(Vs[(kkk + tg) * 136 + n]);
                bf[nt][1] = __float_as_uint(Vs[(kkk + tg + 4) * 136 + n]);
            }
#pragma unroll
            for (int mt = 0; mt < 2; mt++)
#pragma unroll
                for (int nt = 0; nt < 4; nt++)
                    mma8(acco[mt][nt], af[mt], bf[nt]);
        }
    }

#pragma unroll
    for (int mt = 0; mt < 2; mt++)
#pragma unroll
        for (int nt = 0; nt < 4; nt++) {
            int r0 = qb + wm * 32 + mt * 16 + gq;
            int c0 = wn * 32 + nt * 8 + tg * 2;
#pragma unroll
            for (int e = 0; e < 4; e++) {
                int r = r0 + (e >> 1) * 8;
                int c = c0 + (e & 1);
                O[rowbase + (size_t)r * DM + c] = acco[mt][nt][e];
            }
        }
}

// ---------------- launch ----------------
extern "C" void kernel_launch(void* const* d_in, const int* in_sizes, int n_in,
                              void* d_out, int out_size)
{
    const float* x   = (const float*)d_in[0];
    const float* n1w = (const float*)d_in[1];
    const float* n1b = (const float*)d_in[2];
    const float* wq  = (const float*)d_in[3];
    const float* wk  = (const float*)d_in[4];
    const float* wv  = (const float*)d_in[5];
    const float* wg  = (const float*)d_in[6];
    const float* wo  = (const float*)d_in[7];
    const float* n2w = (const float*)d_in[8];
    const float* n2b = (const float*)d_in[9];
    const float* w1  = (const float*)d_in[10];
    const float* w2  = (const float*)d_in[11];
    const float* w3  = (const float*)d_in[12];
    float* out = (float*)d_out;

    float *q, *k, *v, *g, *r, *x1, *f1, *f2;
    bf16 *h_hi, *h_lo, *h2_hi, *h2_lo, *a_hi, *a_lo, *fg_hi, *fg_lo;
    bf16 *wq_hi, *wq_lo, *wk_hi, *wk_lo, *wv_hi, *wv_lo, *wg_hi, *wg_lo, *wo_hi, *wo_lo;
    bf16 *w1_hi, *w1_lo, *w2_hi, *w2_lo, *w3_hi, *w3_lo;

    cudaGetSymbolAddress((void**)&q,  g_q);
    cudaGetSymbolAddress((void**)&k,  g_k);
    cudaGetSymbolAddress((void**)&v,  g_v);
    cudaGetSymbolAddress((void**)&g,  g_g);
    cudaGetSymbolAddress((void**)&r,  g_r);
    cudaGetSymbolAddress((void**)&x1, g_x1);
    cudaGetSymbolAddress((void**)&f1, g_f1);
    cudaGetSymbolAddress((void**)&f2, g_f2);
    cudaGetSymbolAddress((void**)&h_hi,  g_h_hi);
    cudaGetSymbolAddress((void**)&h_lo,  g_h_lo);
    cudaGetSymbolAddress((void**)&h2_hi, g_h2_hi);
    cudaGetSymbolAddress((void**)&h2_lo, g_h2_lo);
    cudaGetSymbolAddress((void**)&a_hi,  g_a_hi);
    cudaGetSymbolAddress((void**)&a_lo,  g_a_lo);
    cudaGetSymbolAddress((void**)&fg_hi, g_fg_hi);
    cudaGetSymbolAddress((void**)&fg_lo, g_fg_lo);
    cudaGetSymbolAddress((void**)&wq_hi, g_wq_hi); cudaGetSymbolAddress((void**)&wq_lo, g_wq_lo);
    cudaGetSymbolAddress((void**)&wk_hi, g_wk_hi); cudaGetSymbolAddress((void**)&wk_lo, g_wk_lo);
    cudaGetSymbolAddress((void**)&wv_hi, g_wv_hi); cudaGetSymbolAddress((void**)&wv_lo, g_wv_lo);
    cudaGetSymbolAddress((void**)&wg_hi, g_wg_hi); cudaGetSymbolAddress((void**)&wg_lo, g_wg_lo);
    cudaGetSymbolAddress((void**)&wo_hi, g_wo_hi); cudaGetSymbolAddress((void**)&wo_lo, g_wo_lo);
    cudaGetSymbolAddress((void**)&w1_hi, g_w1_hi); cudaGetSymbolAddress((void**)&w1_lo, g_w1_lo);
    cudaGetSymbolAddress((void**)&w2_hi, g_w2_hi); cudaGetSymbolAddress((void**)&w2_lo, g_w2_lo);
    cudaGetSymbolAddress((void**)&w3_hi, g_w3_hi); cudaGetSymbolAddress((void**)&w3_lo, g_w3_lo);

    cudaFuncSetAttribute((const void*)gemm_bf16x3,
                         cudaFuncAttributeMaxDynamicSharedMemorySize, GEMM_SMEM);
    cudaFuncSetAttribute((const void*)retention_kernel,
                         cudaFuncAttributeMaxDynamicSharedMemorySize, RET_SMEM);

    // weight conversion (per call; cheap, memory-bound)
    conv_split<<<2048, 256>>>(wq, wq_hi, wq_lo, (size_t)DM * DM);
    conv_split<<<2048, 256>>>(wk, wk_hi, wk_lo, (size_t)DM * DM);
    conv_split<<<2048, 256>>>(wv, wv_hi, wv_lo, (size_t)DM * DM);
    conv_split<<<2048, 256>>>(wg, wg_hi, wg_lo, (size_t)DM * DM);
    conv_split<<<2048, 256>>>(wo, wo_hi, wo_lo, (size_t)DM * DM);
    conv_pad_cols<<<4096, 256>>>(w1, w1_hi, w1_lo, DM, HIDN, HIDP);
    conv_pad_cols<<<4096, 256>>>(w2, w2_hi, w2_lo, DM, HIDN, HIDP);
    conv_pad_rows<<<4096, 256>>>(w3, w3_hi, w3_lo, HIDN, HIDP, DM);

    const dim3 gproj(DM / 128, BSROWS / 128);     // (16, 32)
    const dim3 gffn(HIDP / 128, BSROWS / 128);    // (43, 32)

    ln_kernel<<<BSROWS, 256>>>(x, n1w, n1b, h_hi, h_lo);
    gemm_bf16x3<<<gproj, 256, GEMM_SMEM>>>(h_hi, h_lo, wq_hi, wq_lo, nullptr, q, BSROWS, DM, DM);
    gemm_bf16x3<<<gproj, 256, GEMM_SMEM>>>(h_hi, h_lo, wk_hi, wk_lo, nullptr, k, BSROWS, DM, DM);
    gemm_bf16x3<<<gproj, 256, GEMM_SMEM>>>(h_hi, h_lo, wv_hi, wv_lo, nullptr, v, BSROWS, DM, DM);
    gemm_bf16x3<<<gproj, 256, GEMM_SMEM>>>(h_hi, h_lo, wg_hi, wg_lo, nullptr, g, BSROWS, DM, DM);

    retention_kernel<<<dim3(SL / 64, NB * NH), 256, RET_SMEM>>>(q, k, v, r);
    gn_kernel<<<(BSROWS * NH) / 8, 256>>>(r);
    gate_split<<<4096, 256>>>(g, r, a_hi, a_lo, (size_t)BSROWS * DM);
    gemm_bf16x3<<<gproj, 256, GEMM_SMEM>>>(a_hi, a_lo, wo_hi, wo_lo, x, x1, BSROWS, DM, DM);

    ln_kernel<<<BSROWS, 256>>>(x1, n2w, n2b, h2_hi, h2_lo);
    gemm_bf16x3<<<gffn, 256, GEMM_SMEM>>>(h2_hi, h2_lo, w1_hi, w1_lo, nullptr, f1, BSROWS, HIDP, DM);
    gemm_bf16x3<<<gffn, 256, GEMM_SMEM>>>(h2_hi, h2_lo, w2_hi, w2_lo, nullptr, f2, BSROWS, HIDP, DM);
    gate_split<<<8192, 256>>>(f1, f2, fg_hi, fg_lo, (size_t)BSROWS * HIDP);
    gemm_bf16x3<<<gproj, 256, GEMM_SMEM>>>(fg_hi, fg_lo, w3_hi, w3_lo, x1, out, BSROWS, DM, HIDP);
}

// round 4
// speedup vs baseline: 2.3452x; 1.0236x over previous
#include <cuda_runtime.h>
#include <cuda_bf16.h>
#include <cstdint>
#include <cstddef>

#define NB 2
#define SL 2048
#define DM 2048
#define NH 16
#define DH 128
#define HIDN 5461
#define HIDP 5504           // padded to multiple of 128
#define BSROWS (NB*SL)      // 4096
#define NCH 32              // chunks per sequence (chunk = 64 rows)

typedef __nv_bfloat16 bf16;

// ---------------- scratch (device globals: allocation-free rule) ----------------
__device__ float g_q [(size_t)BSROWS*DM];
__device__ float g_k [(size_t)BSROWS*DM];
__device__ float g_v [(size_t)BSROWS*DM];
__device__ float g_g [(size_t)BSROWS*DM];
__device__ float g_r [(size_t)BSROWS*DM];
__device__ float g_x1[(size_t)BSROWS*DM];
__device__ float g_f1[(size_t)BSROWS*HIDP];
__device__ float g_f2[(size_t)BSROWS*HIDP];
__device__ float g_st[(size_t)NB*NH*NCH*DH*DH];   // chunk states, 64MB

__device__ bf16 g_h_hi [(size_t)BSROWS*DM];
__device__ bf16 g_h_lo [(size_t)BSROWS*DM];
__device__ bf16 g_h2_hi[(size_t)BSROWS*DM];
__device__ bf16 g_h2_lo[(size_t)BSROWS*DM];
__device__ bf16 g_a_hi [(size_t)BSROWS*DM];
__device__ bf16 g_a_lo [(size_t)BSROWS*DM];
__device__ bf16 g_fg_hi[(size_t)BSROWS*HIDP];
__device__ bf16 g_fg_lo[(size_t)BSROWS*HIDP];

__device__ bf16 g_wq_hi[(size_t)DM*DM], g_wq_lo[(size_t)DM*DM];
__device__ bf16 g_wk_hi[(size_t)DM*DM], g_wk_lo[(size_t)DM*DM];
__device__ bf16 g_wv_hi[(size_t)DM*DM], g_wv_lo[(size_t)DM*DM];
__device__ bf16 g_wg_hi[(size_t)DM*DM], g_wg_lo[(size_t)DM*DM];
__device__ bf16 g_wo_hi[(size_t)DM*DM], g_wo_lo[(size_t)DM*DM];
__device__ bf16 g_w1_hi[(size_t)DM*HIDP], g_w1_lo[(size_t)DM*HIDP];
__device__ bf16 g_w2_hi[(size_t)DM*HIDP], g_w2_lo[(size_t)DM*HIDP];
__device__ bf16 g_w3_hi[(size_t)HIDP*DM], g_w3_lo[(size_t)HIDP*DM];

// ---------------- helpers ----------------
__device__ __forceinline__ unsigned f2tf(float x) {
    unsigned r;
    asm("cvt.rna.tf32.f32 %0, %1;" : "=r"(r) : "f"(x));
    return r;
}

__device__ __forceinline__ void split_bf16(float x, bf16& hi, bf16& lo) {
    hi = __float2bfloat16(x);
    lo = __float2bfloat16(x - __bfloat162float(hi));
}

__device__ __forceinline__ void mma8(float* c, const unsigned* a, const unsigned* b) {
    asm volatile(
        "mma.sync.aligned.m16n8k8.row.col.f32.tf32.tf32.f32 "
        "{%0,%1,%2,%3}, {%4,%5,%6,%7}, {%8,%9}, {%0,%1,%2,%3};\n"
        : "+f"(c[0]), "+f"(c[1]), "+f"(c[2]), "+f"(c[3])
        : "r"(a[0]), "r"(a[1]), "r"(a[2]), "r"(a[3]), "r"(b[0]), "r"(b[1]));
}

__device__ __forceinline__ void mma16(float* c, const unsigned* a, const unsigned* b) {
    asm volatile(
        "mma.sync.aligned.m16n8k16.row.col.f32.bf16.bf16.f32 "
        "{%0,%1,%2,%3}, {%4,%5,%6,%7}, {%8,%9}, {%0,%1,%2,%3};\n"
        : "+f"(c[0]), "+f"(c[1]), "+f"(c[2]), "+f"(c[3])
        : "r"(a[0]), "r"(a[1]), "r"(a[2]), "r"(a[3]), "r"(b[0]), "r"(b[1]));
}

__device__ __forceinline__ void ldsm4(unsigned* r, unsigned addr) {
    asm volatile("ldmatrix.sync.aligned.m8n8.x4.shared.b16 {%0,%1,%2,%3}, [%4];\n"
        : "=r"(r[0]), "=r"(r[1]), "=r"(r[2]), "=r"(r[3]) : "r"(addr));
}
__device__ __forceinline__ void ldsm4t(unsigned* r, unsigned addr) {
    asm volatile("ldmatrix.sync.aligned.m8n8.x4.trans.shared.b16 {%0,%1,%2,%3}, [%4];\n"
        : "=r"(r[0]), "=r"(r[1]), "=r"(r[2]), "=r"(r[3]) : "r"(addr));
}
__device__ __forceinline__ void cpa16(unsigned dst, const void* src) {
    asm volatile("cp.async.cg.shared.global [%0], [%1], 16;\n" :: "r"(dst), "l"(src));
}

// ---------------- elementwise converters ----------------
__global__ __launch_bounds__(256)
void conv_split(const float* __restrict__ src, bf16* __restrict__ hi,
                bf16* __restrict__ lo, size_t n)
{
    size_t i = (size_t)blockIdx.x * 256 + threadIdx.x;
    const size_t st = (size_t)gridDim.x * 256;
    for (; i < n; i += st) { split_bf16(src[i], hi[i], lo[i]); }
}

__global__ __launch_bounds__(256)
void conv_pad_cols(const float* __restrict__ src, bf16* __restrict__ hi,
                   bf16* __restrict__ lo, int rows, int scols, int dcols)
{
    size_t n = (size_t)rows * dcols;
    size_t i = (size_t)blockIdx.x * 256 + threadIdx.x;
    const size_t st = (size_t)gridDim.x * 256;
    for (; i < n; i += st) {
        int r = (int)(i / dcols), c = (int)(i % dcols);
        float v = (c < scols) ? src[(size_t)r * scols + c] : 0.f;
        split_bf16(v, hi[i], lo[i]);
    }
}

__global__ __launch_bounds__(256)
void conv_pad_rows(const float* __restrict__ src, bf16* __restrict__ hi,
                   bf16* __restrict__ lo, int srows, int drows, int cols)
{
    size_t n = (size_t)drows * cols;
    size_t i = (size_t)blockIdx.x * 256 + threadIdx.x;
    const size_t st = (size_t)gridDim.x * 256;
    for (; i < n; i += st) {
        int r = (int)(i / cols);
        float v = (r < srows) ? src[i] : 0.f;
        split_bf16(v, hi[i], lo[i]);
    }
}

// ---------------- LayerNorm -> bf16 hi/lo ----------------
__global__ __launch_bounds__(256)
void ln_kernel(const float* __restrict__ x, const float* __restrict__ w,
               const float* __restrict__ b, bf16* __restrict__ ohi,
               bf16* __restrict__ olo)
{
    __shared__ float red[16];
    const int row = blockIdx.x;
    const float* xr = x + (size_t)row * DM;
    float vals[8];
    float s = 0.f, ss = 0.f;
#pragma unroll
    for (int j = 0; j < 8; j++) {
        float v = xr[threadIdx.x + j * 256];
        vals[j] = v; s += v; ss += v * v;
    }
#pragma unroll
    for (int o = 16; o > 0; o >>= 1) {
        s  += __shfl_xor_sync(0xFFFFFFFFu, s,  o);
        ss += __shfl_xor_sync(0xFFFFFFFFu, ss, o);
    }
    const int warp = threadIdx.x >> 5, lane = threadIdx.x & 31;
    if (lane == 0) { red[warp] = s; red[8 + warp] = ss; }
    __syncthreads();
    s = 0.f; ss = 0.f;
#pragma unroll
    for (int k = 0; k < 8; k++) { s += red[k]; ss += red[8 + k]; }
    const float mean = s * (1.f / DM);
    const float var  = ss * (1.f / DM) - mean * mean;
    const float rstd = rsqrtf(var + 1e-5f);
#pragma unroll
    for (int j = 0; j < 8; j++) {
        int col = threadIdx.x + j * 256;
        float o = (vals[j] - mean) * rstd * w[col] + b[col];
        split_bf16(o, ohi[(size_t)row * DM + col], olo[(size_t)row * DM + col]);
    }
}

// ---------------- fused per-head GroupNorm + silu gate -> bf16 hi/lo ----------------
__global__ __launch_bounds__(256)
void gn_gate(const float* __restrict__ g, const float* __restrict__ r,
             bf16* __restrict__ hi, bf16* __restrict__ lo)
{
    const int gi = blockIdx.x * 8 + (threadIdx.x >> 5);
    const int lane = threadIdx.x & 31;
    const size_t base = (size_t)gi * DH + lane * 4;
    float4 v = *reinterpret_cast<const float4*>(r + base);
    float s  = v.x + v.y + v.z + v.w;
    float ss = v.x*v.x + v.y*v.y + v.z*v.z + v.w*v.w;
#pragma unroll
    for (int o = 16; o > 0; o >>= 1) {
        s  += __shfl_xor_sync(0xFFFFFFFFu, s,  o);
        ss += __shfl_xor_sync(0xFFFFFFFFu, ss, o);
    }
    const float mean = s * (1.f / DH);
    const float var  = ss * (1.f / DH) - mean * mean;
    const float rstd = rsqrtf(var + 1e-5f);
    float4 gv = *reinterpret_cast<const float4*>(g + base);
    float o0 = (gv.x / (1.f + expf(-gv.x))) * ((v.x - mean) * rstd);
    float o1 = (gv.y / (1.f + expf(-gv.y))) * ((v.y - mean) * rstd);
    float o2 = (gv.z / (1.f + expf(-gv.z))) * ((v.z - mean) * rstd);
    float o3 = (gv.w / (1.f + expf(-gv.w))) * ((v.w - mean) * rstd);
    split_bf16(o0, hi[base + 0], lo[base + 0]);
    split_bf16(o1, hi[base + 1], lo[base + 1]);
    split_bf16(o2, hi[base + 2], lo[base + 2]);
    split_bf16(o3, hi[base + 3], lo[base + 3]);
}

// ---------------- silu(a) * b -> bf16 hi/lo ----------------
__global__ __launch_bounds__(256)
void gate_split(const float* __restrict__ ga, const float* __restrict__ gb,
                bf16* __restrict__ hi, bf16* __restrict__ lo, size_t n)
{
    size_t i = (size_t)blockIdx.x * 256 + threadIdx.x;
    const size_t st = (size_t)gridDim.x * 256;
    for (; i < n; i += st) {
        float x = ga[i];
        float v = (x / (1.f + expf(-x))) * gb[i];
        split_bf16(v, hi[i], lo[i]);
    }
}

// ---------------- bf16x3 GEMM (proven R1 kernel) ----------------
#define A_BUFB 10240u   // 128 rows * 80B
#define B_BUFB 8704u    // 32 rows * 272B
#define GEMM_SMEM (4*A_BUFB + 4*B_BUFB)   // 75776 B

__device__ __forceinline__ void gemm_prefetch(
    const bf16* __restrict__ Ahi, const bf16* __restrict__ Alo,
    const bf16* __restrict__ Bhi, const bf16* __restrict__ Blo,
    unsigned sA, unsigned sB, int buf, int bm, int bn, int k0, int K, int N, int tid)
{
#pragma unroll
    for (int i = 0; i < 2; i++) {
        int c = tid + i * 256;
        int row = c >> 2, chn = c & 3;
        size_t go = (size_t)(bm + row) * K + k0 + chn * 8;
        unsigned so = (unsigned)buf * A_BUFB + row * 80u + chn * 16u;
        cpa16(sA + so, Ahi + go);
        cpa16(sA + 2u * A_BUFB + so, Alo + go);
    }
#pragma unroll
    for (int i = 0; i < 2; i++) {
        int c = tid + i * 256;
        int row = c >> 4, chn = c & 15;
        size_t go = (size_t)(k0 + row) * N + bn + chn * 8;
        unsigned so = (unsigned)buf * B_BUFB + row * 272u + chn * 16u;
        cpa16(sB + so, Bhi + go);
        cpa16(sB + 2u * B_BUFB + so, Blo + go);
    }
}

__global__ __launch_bounds__(256, 1)
void gemm_bf16x3(const bf16* __restrict__ Ahi, const bf16* __restrict__ Alo,
                 const bf16* __restrict__ Bhi, const bf16* __restrict__ Blo,
                 const float* __restrict__ Res, float* __restrict__ C,
                 int M, int N, int K)
{
    extern __shared__ __align__(16) char smemraw[];
    const unsigned sA = (unsigned)__cvta_generic_to_shared(smemraw);
    const unsigned sB = sA + 4u * A_BUFB;

    const int tid  = threadIdx.x;
    const int lane = tid & 31;
    const int warp = tid >> 5;
    const int wm = warp >> 2;
    const int wn = warp & 3;
    const int bm = blockIdx.y * 128;
    const int bn = blockIdx.x * 128;

    const unsigned laneA = (unsigned)(((lane & 7) + ((lane >> 3) & 1) * 8) * 80 + (lane >> 4) * 16);
    const unsigned laneB = (unsigned)(((lane & 7) + ((lane >> 3) & 1) * 8) * 272 + (lane >> 4) * 16);

    float acc[4][4][4];
#pragma unroll
    for (int a = 0; a < 4; a++)
#pragma unroll
        for (int b = 0; b < 4; b++)
#pragma unroll
            for (int c = 0; c < 4; c++) acc[a][b][c] = 0.f;

    const int nk = K >> 5;
    gemm_prefetch(Ahi, Alo, Bhi, Blo, sA, sB, 0, bm, bn, 0, K, N, tid);
    asm volatile("cp.async.commit_group;\n" ::: "memory");

    for (int t = 0; t < nk; t++) {
        if (t + 1 < nk) {
            gemm_prefetch(Ahi, Alo, Bhi, Blo, sA, sB, (t + 1) & 1, bm, bn, (t + 1) * 32, K, N, tid);
            asm volatile("cp.async.commit_group;\n" ::: "memory");
            asm volatile("cp.async.wait_group 1;\n" ::: "memory");
        } else {
            asm volatile("cp.async.wait_group 0;\n" ::: "memory");
        }
        __syncthreads();

        const int buf = t & 1;
        const unsigned aBase = sA + (unsigned)buf * A_BUFB + (unsigned)(wm * 64 * 80) + laneA;
        const unsigned bBase = sB + (unsigned)buf * B_BUFB + (unsigned)(wn * 32 * 2) + laneB;

#pragma unroll
        for (int ks = 0; ks < 2; ks++) {
            unsigned ah[4][4], al[4][4], bh[2][4], bl[2][4];
#pragma unroll
            for (int mt = 0; mt < 4; mt++) {
                unsigned ad = aBase + (unsigned)(mt * 16 * 80 + ks * 32);
                ldsm4(ah[mt], ad);
                ldsm4(al[mt], ad + 2u * A_BUFB);
            }
#pragma unroll
            for (int p = 0; p < 2; p++) {
                unsigned bd = bBase + (unsigned)(ks * 16 * 272 + p * 32);
                ldsm4t(bh[p], bd);
                ldsm4t(bl[p], bd + 2u * B_BUFB);
            }
#pragma unroll
            for (int mt = 0; mt < 4; mt++)
#pragma unroll
                for (int p = 0; p < 2; p++) {
                    mma16(acc[mt][2*p],   ah[mt], bh[p]);
                    mma16(acc[mt][2*p],   ah[mt], bl[p]);
                    mma16(acc[mt][2*p],   al[mt], bh[p]);
                    mma16(acc[mt][2*p+1], ah[mt], bh[p] + 2);
                    mma16(acc[mt][2*p+1], ah[mt], bl[p] + 2);
                    mma16(acc[mt][2*p+1], al[mt], bh[p] + 2);
                }
        }
        __syncthreads();
    }

#pragma unroll
    for (int mt = 0; mt < 4; mt++)
#pragma unroll
        for (int nt = 0; nt < 4; nt++) {
            int r0 = bm + wm * 64 + mt * 16 + (lane >> 2);
            int c0 = bn + wn * 32 + nt * 8 + (lane & 3) * 2;
#pragma unroll
            for (int half = 0; half < 2; half++) {
                int r = r0 + half * 8;
                float2 v = make_float2(acc[mt][nt][half * 2], acc[mt][nt][half * 2 + 1]);
                if (Res) {
                    float2 rv = *reinterpret_cast<const float2*>(&Res[(size_t)r * N + c0]);
                    v.x += rv.x; v.y += rv.y;
                }
                *reinterpret_cast<float2*>(&C[(size_t)r * N + c0]) = v;
            }
        }
}

// ================= chunkwise retention =================
// Phase 1: per-chunk state contribution C_i = sum_t w_t k_t v_t^T, w_t = dh^-0.5 * gamma^(63-t_loc)
#define RC_SMEM ((128*68 + 64*136)*4)

__global__ __launch_bounds__(256, 1)
void ret_contrib(const float* __restrict__ K, const float* __restrict__ V,
                 float* __restrict__ CS)
{
    extern __shared__ float smc[];
    float* KsT = smc;              // [128 dh][68] (transposed, weighted)
    float* Vs  = KsT + 128 * 68;   // [64 t][136]

    const int tid  = threadIdx.x;
    const int lane = tid & 31;
    const int warp = tid >> 5;
    const int gq = lane >> 2;
    const int tg = lane & 3;
    const int wm = warp >> 2;      // 0..1 over dh(128)
    const int wn = warp & 3;       // 0..3 over v-dim(128)
    const int chunk = blockIdx.x;
    const int bh = blockIdx.y;
    const int b = bh >> 4, h = bh & 15;
    const int kb = chunk * 64;

    const float gamma = 1.f - exp2f(-5.f - (float)h);
    const float lg = log2f(gamma);
    const size_t rowbase = (size_t)(b * SL) * DM + (size_t)h * DH;

#pragma unroll
    for (int it = 0; it < 32; it++) {
        int idx = tid + it * 256;
        int t = idx >> 7, d = idx & 127;
        size_t gidx = rowbase + (size_t)(kb + t) * DM + d;
        float w = 0.08838834764831845f * exp2f((float)(63 - t) * lg);
        KsT[d * 68 + t] = __uint_as_float(f2tf(w * K[gidx]));
        Vs[t * 136 + d] = __uint_as_float(f2tf(V[gidx]));
    }
    __syncthreads();

    float acc[4][4][4];
#pragma unroll
    for (int a = 0; a < 4; a++)
#pragma unroll
        for (int bq = 0; bq < 4; bq++)
#pragma unroll
            for (int c = 0; c < 4; c++) acc[a][bq][c] = 0.f;

#pragma unroll
    for (int ks = 0; ks < 8; ks++) {
        const int kkk = ks * 8;
        unsigned af[4][4], bf[4][2];
#pragma unroll
        for (int mt = 0; mt < 4; mt++) {
            int m = wm * 64 + mt * 16 + gq;
            af[mt][0] = __float_as_uint(KsT[m * 68 + kkk + tg]);
            af[mt][1] = __float_as_uint(KsT[(m + 8) * 68 + kkk + tg]);
            af[mt][2] = __float_as_uint(KsT[m * 68 + kkk + tg + 4]);
            af[mt][3] = __float_as_uint(KsT[(m + 8) * 68 + kkk + tg + 4]);
        }
#pragma unroll
        for (int nt = 0; nt < 4; nt++) {
            int n = wn * 32 + nt * 8 + gq;
            bf[nt][0] = __float_as_uint(Vs[(kkk + tg) * 136 + n]);
            bf[nt][1] = __float_as_uint(Vs[(kkk + tg + 4) * 136 + n]);
        }
#pragma unroll
        for (int mt = 0; mt < 4; mt++)
#pragma unroll
            for (int nt = 0; nt < 4; nt++)
                mma8(acc[mt][nt], af[mt], bf[nt]);
    }

    float* outp = CS + ((size_t)bh * NCH + chunk) * (DH * DH);
#pragma unroll
    for (int mt = 0; mt < 4; mt++)
#pragma unroll
        for (int nt = 0; nt < 4; nt++) {
            int r0 = wm * 64 + mt * 16 + gq;
            int c0 = wn * 32 + nt * 8 + tg * 2;
#pragma unroll
            for (int e = 0; e < 4; e++) {
                int r = r0 + (e >> 1) * 8;
                int c = c0 + (e & 1);
                outp[r * DH + c] = acc[mt][nt][e];
            }
        }
}

// Phase 2: in-place exclusive scan over chunks: state_i (written) = state BEFORE chunk i
__global__ __launch_bounds__(512)
void ret_scan(float* __restrict__ CS)
{
    const int bh = blockIdx.x;
    const int h = bh & 15;
    const float gamma = 1.f - exp2f(-5.f - (float)h);
    const float dec = exp2f(64.f * log2f(gamma));   // gamma^64
    float* base = CS + (size_t)bh * NCH * (DH * DH);
    const int tid = threadIdx.x;

    float s[32];
#pragma unroll
    for (int j = 0; j < 32; j++) s[j] = 0.f;
    for (int i = 0; i < NCH; i++) {
        float* p = base + (size_t)i * (DH * DH);
#pragma unroll
        for (int j = 0; j < 32; j++) {
            int e = tid + j * 512;
            float c = p[e];
            p[e] = s[j];
            s[j] = s[j] * dec + c;
        }
    }
}

// Phase 3: O = mask(Q K^T) V + diag(gamma^(s_loc+1)) Q State
#define RO_SMEM ((64*132*2 + 64*136 + 64*68 + 128*136 + 128 + 64)*4)

__global__ __launch_bounds__(256, 1)
void ret_out(const float* __restrict__ Q, const float* __restrict__ Kt,
             const float* __restrict__ V, const float* __restrict__ CS,
             float* __restrict__ O)
{
    extern __shared__ float smr[];
    float* Qs  = smr;               // [64][132]
    float* Ks  = Qs + 64 * 132;     // [64][132]
    float* Vs  = Ks + 64 * 132;     // [64][136]
    float* Ss  = Vs + 64 * 136;     // [64][68]
    float* Sts = Ss + 64 * 68;      // [128][136]  state
    float* dp  = Sts + 128 * 136;   // [128]
    float* dp2 = dp + 128;          // [64]

    const int tid  = threadIdx.x;
    const int lane = tid & 31;
    const int warp = tid >> 5;
    const int gq = lane >> 2;
    const int tg = lane & 3;
    const int wm = warp >> 2;
    const int wn = warp & 3;
    const int chunk = blockIdx.x;
    const int bh = blockIdx.y;
    const int b = bh >> 4, h = bh & 15;
    const int qb = chunk * 64;

    const float gamma = 1.f - exp2f(-5.f - (float)h);
    const float lg = log2f(gamma);
    const size_t rowbase = (size_t)(b * SL) * DM + (size_t)h * DH;
    const float* stp = CS + ((size_t)bh * NCH + chunk) * (DH * DH);

#pragma unroll
    for (int it = 0; it < 32; it++) {
        int idx = tid + it * 256;
        int r = idx >> 7, d = idx & 127;
        size_t gidx = rowbase + (size_t)(qb + r) * DM + d;
        Qs[r * 132 + d] = __uint_as_float(f2tf(Q[gidx]));
        Ks[r * 132 + d] = __uint_as_float(f2tf(Kt[gidx]));
        Vs[r * 136 + d] = __uint_as_float(f2tf(V[gidx]));
    }
#pragma unroll
    for (int it = 0; it < 64; it++) {
        int idx = tid + it * 256;
        int r = idx >> 7, d = idx & 127;
        Sts[r * 136 + d] = __uint_as_float(f2tf(stp[idx]));
    }
    if (tid < 128) {
        int e = tid - 63;
        dp[tid] = (e < 0) ? 0.f : 0.08838834764831845f * exp2f((float)e * lg);
    }
    if (tid < 64) dp2[tid] = exp2f((float)(tid + 1) * lg);
    __syncthreads();

    // cross term: acco = Q @ State
    float acco[2][4][4];
#pragma unroll
    for (int a = 0; a < 2; a++)
#pragma unroll
        for (int bq = 0; bq < 4; bq++)
#pragma unroll
            for (int c = 0; c < 4; c++) acco[a][bq][c] = 0.f;

#pragma unroll
    for (int ks = 0; ks < 16; ks++) {
        const int kkk = ks * 8;
        unsigned af[2][4], bf[4][2];
#pragma unroll
        for (int mt = 0; mt < 2; mt++) {
            int m = wm * 32 + mt * 16 + gq;
            af[mt][0] = __float_as_uint(Qs[m * 132 + kkk + tg]);
            af[mt][1] = __float_as_uint(Qs[(m + 8) * 132 + kkk + tg]);
            af[mt][2] = __float_as_uint(Qs[m * 132 + kkk + tg + 4]);
            af[mt][3] = __float_as_uint(Qs[(m + 8) * 132 + kkk + tg + 4]);
        }
#pragma unroll
        for (int nt = 0; nt < 4; nt++) {
            int n = wn * 32 + nt * 8 + gq;
            bf[nt][0] = __float_as_uint(Sts[(kkk + tg) * 136 + n]);
            bf[nt][1] = __float_as_uint(Sts[(kkk + tg + 4) * 136 + n]);
        }
#pragma unroll
        for (int mt = 0; mt < 2; mt++)
#pragma unroll
            for (int nt = 0; nt < 4; nt++)
                mma8(acco[mt][nt], af[mt], bf[nt]);
    }
    // scale cross term by gamma^(s_loc+1)
#pragma unroll
    for (int mt = 0; mt < 2; mt++) {
        int r0 = wm * 32 + mt * 16 + gq;
        float sc0 = dp2[r0], sc1 = dp2[r0 + 8];
#pragma unroll
        for (int nt = 0; nt < 4; nt++) {
            acco[mt][nt][0] *= sc0; acco[mt][nt][1] *= sc0;
            acco[mt][nt][2] *= sc1; acco[mt][nt][3] *= sc1;
        }
    }

    // intra: S = mask(Q K^T) * decay
    float accs[2][2][4];
#pragma unroll
    for (int a = 0; a < 2; a++)
#pragma unroll
        for (int bq = 0; bq < 2; bq++)
#pragma unroll
            for (int c = 0; c < 4; c++) accs[a][bq][c] = 0.f;
#pragma unroll
    for (int ks = 0; ks < 16; ks++) {
        const int kkk = ks * 8;
        unsigned af[2][4], bf[2][2];
#pragma unroll
        for (int mt = 0; mt < 2; mt++) {
            int m = wm * 32 + mt * 16 + gq;
            af[mt][0] = __float_as_uint(Qs[m * 132 + kkk + tg]);
            af[mt][1] = __float_as_uint(Qs[(m + 8) * 132 + kkk + tg]);
            af[mt][2] = __float_as_uint(Qs[m * 132 + kkk + tg + 4]);
            af[mt][3] = __float_as_uint(Qs[(m + 8) * 132 + kkk + tg + 4]);
        }
#pragma unroll
        for (int nt = 0; nt < 2; nt++) {
            int n = wn * 16 + nt * 8 + gq;
            bf[nt][0] = __float_as_uint(Ks[n * 132 + kkk + tg]);
            bf[nt][1] = __float_as_uint(Ks[n * 132 + kkk + tg + 4]);
        }
#pragma unroll
        for (int mt = 0; mt < 2; mt++)
#pragma unroll
            for (int nt = 0; nt < 2; nt++)
                mma8(accs[mt][nt], af[mt], bf[nt]);
    }
#pragma unroll
    for (int mt = 0; mt < 2; mt++)
#pragma unroll
        for (int nt = 0; nt < 2; nt++) {
            int sr0 = wm * 32 + mt * 16 + gq;
            int tc0 = wn * 16 + nt * 8 + tg * 2;
#pragma unroll
            for (int e = 0; e < 4; e++) {
                int sr = sr0 + (e >> 1) * 8;
                int tc = tc0 + (e & 1);
                float coeff = dp[sr - tc + 63];
                Ss[sr * 68 + tc] = __uint_as_float(f2tf(accs[mt][nt][e] * coeff));
            }
        }
    __syncthreads();

#pragma unroll
    for (int ks = 0; ks < 8; ks++) {
        const int kkk = ks * 8;
        unsigned af[2][4], bf[4][2];
#pragma unroll
        for (int mt = 0; mt < 2; mt++) {
            int m = wm * 32 + mt * 16 + gq;
            af[mt][0] = __float_as_uint(Ss[m * 68 + kkk + tg]);
            af[mt][1] = __float_as_uint(Ss[(m + 8) * 68 + kkk + tg]);
            af[mt][2] = __float_as_uint(Ss[m * 68 + kkk + tg + 4]);
            af[mt][3] = __float_as_uint(Ss[(m + 8) * 68 + kkk + tg + 4]);
        }
#pragma unroll
        for (int nt = 0; nt < 4; nt++) {
            int n = wn * 32 + nt * 8 + gq;
            bf[nt][0] = __float_as_uint(Vs[(kkk + tg) * 136 + n]);
            bf[nt][1] = __float_as_uint(Vs[(kkk + tg + 4) * 136 + n]);
        }
#pragma unroll
        for (int mt = 0; mt < 2; mt++)
#pragma unroll
            for (int nt = 0; nt < 4; nt++)
                mma8(acco[mt][nt], af[mt], bf[nt]);
    }

#pragma unroll
    for (int mt = 0; mt < 2; mt++)
#pragma unroll
        for (int nt = 0; nt < 4; nt++) {
            int r0 = qb + wm * 32 + mt * 16 + gq;
            int c0 = wn * 32 + nt * 8 + tg * 2;
#pragma unroll
            for (int e = 0; e < 4; e++) {
                int r = r0 + (e >> 1) * 8;
                int c = c0 + (e & 1);
                O[rowbase + (size_t)r * DM + c] = acco[mt][nt][e];
            }
        }
}

// ---------------- launch ----------------
extern "C" void kernel_launch(void* const* d_in, const int* in_sizes, int n_in,
                              void* d_out, int out_size)
{
    const float* x   = (const float*)d_in[0];
    const float* n1w = (const float*)d_in[1];
    const float* n1b = (const float*)d_in[2];
    const float* wq  = (const float*)d_in[3];
    const float* wk  = (const float*)d_in[4];
    const float* wv  = (const float*)d_in[5];
    const float* wg  = (const float*)d_in[6];
    const float* wo  = (const float*)d_in[7];
    const float* n2w = (const float*)d_in[8];
    const float* n2b = (const float*)d_in[9];
    const float* w1  = (const float*)d_in[10];
    const float* w2  = (const float*)d_in[11];
    const float* w3  = (const float*)d_in[12];
    float* out = (float*)d_out;

    float *q, *k, *v, *g, *r, *x1, *f1, *f2, *cs;
    bf16 *h_hi, *h_lo, *h2_hi, *h2_lo, *a_hi, *a_lo, *fg_hi, *fg_lo;
    bf16 *wq_hi, *wq_lo, *wk_hi, *wk_lo, *wv_hi, *wv_lo, *wg_hi, *wg_lo, *wo_hi, *wo_lo;
    bf16 *w1_hi, *w1_lo, *w2_hi, *w2_lo, *w3_hi, *w3_lo;

    cudaGetSymbolAddress((void**)&q,  g_q);
    cudaGetSymbolAddress((void**)&k,  g_k);
    cudaGetSymbolAddress((void**)&v,  g_v);
    cudaGetSymbolAddress((void**)&g,  g_g);
    cudaGetSymbolAddress((void**)&r,  g_r);
    cudaGetSymbolAddress((void**)&x1, g_x1);
    cudaGetSymbolAddress((void**)&f1, g_f1);
    cudaGetSymbolAddress((void**)&f2, g_f2);
    cudaGetSymbolAddress((void**)&cs, g_st);
    cudaGetSymbolAddress((void**)&h_hi,  g_h_hi);
    cudaGetSymbolAddress((void**)&h_lo,  g_h_lo);
    cudaGetSymbolAddress((void**)&h2_hi, g_h2_hi);
    cudaGetSymbolAddress((void**)&h2_lo, g_h2_lo);
    cudaGetSymbolAddress((void**)&a_hi,  g_a_hi);
    cudaGetSymbolAddress((void**)&a_lo,  g_a_lo);
    cudaGetSymbolAddress((void**)&fg_hi, g_fg_hi);
    cudaGetSymbolAddress((void**)&fg_lo, g_fg_lo);
    cudaGetSymbolAddress((void**)&wq_hi, g_wq_hi); cudaGetSymbolAddress((void**)&wq_lo, g_wq_lo);
    cudaGetSymbolAddress((void**)&wk_hi, g_wk_hi); cudaGetSymbolAddress((void**)&wk_lo, g_wk_lo);
    cudaGetSymbolAddress((void**)&wv_hi, g_wv_hi); cudaGetSymbolAddress((void**)&wv_lo, g_wv_lo);
    cudaGetSymbolAddress((void**)&wg_hi, g_wg_hi); cudaGetSymbolAddress((void**)&wg_lo, g_wg_lo);
    cudaGetSymbolAddress((void**)&wo_hi, g_wo_hi); cudaGetSymbolAddress((void**)&wo_lo, g_wo_lo);
    cudaGetSymbolAddress((void**)&w1_hi, g_w1_hi); cudaGetSymbolAddress((void**)&w1_lo, g_w1_lo);
    cudaGetSymbolAddress((void**)&w2_hi, g_w2_hi); cudaGetSymbolAddress((void**)&w2_lo, g_w2_lo);
    cudaGetSymbolAddress((void**)&w3_hi, g_w3_hi); cudaGetSymbolAddress((void**)&w3_lo, g_w3_lo);

    cudaFuncSetAttribute((const void*)gemm_bf16x3,
                         cudaFuncAttributeMaxDynamicSharedMemorySize, GEMM_SMEM);
    cudaFuncSetAttribute((const void*)ret_contrib,
                         cudaFuncAttributeMaxDynamicSharedMemorySize, RC_SMEM);
    cudaFuncSetAttribute((const void*)ret_out,
                         cudaFuncAttributeMaxDynamicSharedMemorySize, RO_SMEM);

    // weight conversion
    conv_split<<<2048, 256>>>(wq, wq_hi, wq_lo, (size_t)DM * DM);
    conv_split<<<2048, 256>>>(wk, wk_hi, wk_lo, (size_t)DM * DM);
    conv_split<<<2048, 256>>>(wv, wv_hi, wv_lo, (size_t)DM * DM);
    conv_split<<<2048, 256>>>(wg, wg_hi, wg_lo, (size_t)DM * DM);
    conv_split<<<2048, 256>>>(wo, wo_hi, wo_lo, (size_t)DM * DM);
    conv_pad_cols<<<4096, 256>>>(w1, w1_hi, w1_lo, DM, HIDN, HIDP);
    conv_pad_cols<<<4096, 256>>>(w2, w2_hi, w2_lo, DM, HIDN, HIDP);
    conv_pad_rows<<<4096, 256>>>(w3, w3_hi, w3_lo, HIDN, HIDP, DM);

    const dim3 gproj(DM / 128, BSROWS / 128);     // (16, 32)
    const dim3 gffn(HIDP / 128, BSROWS / 128);    // (43, 32)

    ln_kernel<<<BSROWS, 256>>>(x, n1w, n1b, h_hi, h_lo);
    gemm_bf16x3<<<gproj, 256, GEMM_SMEM>>>(h_hi, h_lo, wq_hi, wq_lo, nullptr, q, BSROWS, DM, DM);
    gemm_bf16x3<<<gproj, 256, GEMM_SMEM>>>(h_hi, h_lo, wk_hi, wk_lo, nullptr, k, BSROWS, DM, DM);
    gemm_bf16x3<<<gproj, 256, GEMM_SMEM>>>(h_hi, h_lo, wv_hi, wv_lo, nullptr, v, BSROWS, DM, DM);
    gemm_bf16x3<<<gproj, 256, GEMM_SMEM>>>(h_hi, h_lo, wg_hi, wg_lo, nullptr, g, BSROWS, DM, DM);

    // chunkwise retention
    ret_contrib<<<dim3(NCH, NB * NH), 256, RC_SMEM>>>(k, v, cs);
    ret_scan<<<NB * NH, 512>>>(cs);
    ret_out<<<dim3(NCH, NB * NH), 256, RO_SMEM>>>(q, k, v, cs, r);

    gn_gate<<<(BSROWS * NH) / 8, 256>>>(g, r, a_hi, a_lo);
    gemm_bf16x3<<<gproj, 256, GEMM_SMEM>>>(a_hi, a_lo, wo_hi, wo_lo, x, x1, BSROWS, DM, DM);

    ln_kernel<<<BSROWS, 256>>>(x1, n2w, n2b, h2_hi, h2_lo);
    gemm_bf16x3<<<gffn, 256, GEMM_SMEM>>>(h2_hi, h2_lo, w1_hi, w1_lo, nullptr, f1, BSROWS, HIDP, DM);
    gemm_bf16x3<<<gffn, 256, GEMM_SMEM>>>(h2_hi, h2_lo, w2_hi, w2_lo, nullptr, f2, BSROWS, HIDP, DM);
    gate_split<<<8192, 256>>>(f1, f2, fg_hi, fg_lo, (size_t)BSROWS * HIDP);
    gemm_bf16x3<<<gproj, 256, GEMM_SMEM>>>(fg_hi, fg_lo, w3_hi, w3_lo, x1, out, BSROWS, DM, HIDP);
}

// round 5
// speedup vs baseline: 2.5890x; 1.1040x over previous
#include <cuda_runtime.h>
#include <cuda_bf16.h>
#include <cstdint>
#include <cstddef>

#define NB 2
#define SL 2048
#define DM 2048
#define NH 16
#define DH 128
#define HIDN 5461
#define HIDP 5504           // padded to multiple of 128
#define BSROWS (NB*SL)      // 4096
#define NCH 32              // chunks per sequence (chunk = 64 rows)
#define QST 8192            // packed qkvg row stride
#define FST 11008           // packed f1|f2 row stride

typedef __nv_bfloat16 bf16;

// ---------------- scratch (device globals: allocation-free rule) ----------------
__device__ float g_qkvg[(size_t)BSROWS*QST];      // q|k|v|g packed
__device__ float g_r [(size_t)BSROWS*DM];
__device__ float g_x1[(size_t)BSROWS*DM];
__device__ float g_f12[(size_t)BSROWS*FST];       // f1|f2 packed
__device__ float g_st[(size_t)NB*NH*NCH*DH*DH];   // chunk states

__device__ bf16 g_h_hi [(size_t)BSROWS*DM];
__device__ bf16 g_h_lo [(size_t)BSROWS*DM];
__device__ bf16 g_h2_hi[(size_t)BSROWS*DM];
__device__ bf16 g_h2_lo[(size_t)BSROWS*DM];
__device__ bf16 g_a_hi [(size_t)BSROWS*DM];
__device__ bf16 g_a_lo [(size_t)BSROWS*DM];
__device__ bf16 g_fg_hi[(size_t)BSROWS*HIDP];
__device__ bf16 g_fg_lo[(size_t)BSROWS*HIDP];

__device__ bf16 g_wqkvg_hi[(size_t)DM*QST], g_wqkvg_lo[(size_t)DM*QST];  // [K][8192]
__device__ bf16 g_wo_hi[(size_t)DM*DM],  g_wo_lo[(size_t)DM*DM];         // [K][2048]
__device__ bf16 g_w12_hi[(size_t)DM*FST], g_w12_lo[(size_t)DM*FST];      // [K][11008]
__device__ bf16 g_w3_hi[(size_t)HIDP*DM], g_w3_lo[(size_t)HIDP*DM];      // [K=HIDP][2048]

// ---------------- helpers ----------------
__device__ __forceinline__ unsigned f2tf(float x) {
    unsigned r;
    asm("cvt.rna.tf32.f32 %0, %1;" : "=r"(r) : "f"(x));
    return r;
}

__device__ __forceinline__ void split_bf16(float x, bf16& hi, bf16& lo) {
    hi = __float2bfloat16(x);
    lo = __float2bfloat16(x - __bfloat162float(hi));
}

__device__ __forceinline__ void mma8(float* c, const unsigned* a, const unsigned* b) {
    asm volatile(
        "mma.sync.aligned.m16n8k8.row.col.f32.tf32.tf32.f32 "
        "{%0,%1,%2,%3}, {%4,%5,%6,%7}, {%8,%9}, {%0,%1,%2,%3};\n"
        : "+f"(c[0]), "+f"(c[1]), "+f"(c[2]), "+f"(c[3])
        : "r"(a[0]), "r"(a[1]), "r"(a[2]), "r"(a[3]), "r"(b[0]), "r"(b[1]));
}

__device__ __forceinline__ void mma16(float* c, const unsigned* a, const unsigned* b) {
    asm volatile(
        "mma.sync.aligned.m16n8k16.row.col.f32.bf16.bf16.f32 "
        "{%0,%1,%2,%3}, {%4,%5,%6,%7}, {%8,%9}, {%0,%1,%2,%3};\n"
        : "+f"(c[0]), "+f"(c[1]), "+f"(c[2]), "+f"(c[3])
        : "r"(a[0]), "r"(a[1]), "r"(a[2]), "r"(a[3]), "r"(b[0]), "r"(b[1]));
}

__device__ __forceinline__ void ldsm4(unsigned* r, unsigned addr) {
    asm volatile("ldmatrix.sync.aligned.m8n8.x4.shared.b16 {%0,%1,%2,%3}, [%4];\n"
        : "=r"(r[0]), "=r"(r[1]), "=r"(r[2]), "=r"(r[3]) : "r"(addr));
}
__device__ __forceinline__ void ldsm4t(unsigned* r, unsigned addr) {
    asm volatile("ldmatrix.sync.aligned.m8n8.x4.trans.shared.b16 {%0,%1,%2,%3}, [%4];\n"
        : "=r"(r[0]), "=r"(r[1]), "=r"(r[2]), "=r"(r[3]) : "r"(addr));
}
__device__ __forceinline__ void cpa16(unsigned dst, const void* src) {
    asm volatile("cp.async.cg.shared.global [%0], [%1], 16;\n" :: "r"(dst), "l"(src));
}

// ---------------- weight packers ----------------
__global__ __launch_bounds__(256)
void conv_qkvg(const float* __restrict__ wq, const float* __restrict__ wk,
               const float* __restrict__ wv, const float* __restrict__ wg,
               bf16* __restrict__ hi, bf16* __restrict__ lo)
{
    const size_t n = (size_t)DM * QST;
    size_t i = (size_t)blockIdx.x * 256 + threadIdx.x;
    const size_t st = (size_t)gridDim.x * 256;
    for (; i < n; i += st) {
        size_t k = i >> 13;
        int c = (int)(i & (QST - 1));
        int proj = c >> 11, col = c & 2047;
        const float* s = (proj == 0) ? wq : (proj == 1) ? wk : (proj == 2) ? wv : wg;
        split_bf16(s[k * DM + col], hi[i], lo[i]);
    }
}

__global__ __launch_bounds__(256)
void conv_wo(const float* __restrict__ src, bf16* __restrict__ hi, bf16* __restrict__ lo)
{
    const size_t n = (size_t)DM * DM;
    size_t i = (size_t)blockIdx.x * 256 + threadIdx.x;
    const size_t st = (size_t)gridDim.x * 256;
    for (; i < n; i += st) split_bf16(src[i], hi[i], lo[i]);
}

__global__ __launch_bounds__(256)
void conv_w12(const float* __restrict__ w1, const float* __restrict__ w2,
              bf16* __restrict__ hi, bf16* __restrict__ lo)
{
    const size_t n = (size_t)DM * FST;
    size_t i = (size_t)blockIdx.x * 256 + threadIdx.x;
    const size_t st = (size_t)gridDim.x * 256;
    for (; i < n; i += st) {
        size_t k = i / FST;
        int c = (int)(i - k * FST);
        float v;
        if (c < HIDP) v = (c < HIDN) ? w1[k * HIDN + c] : 0.f;
        else { int c2 = c - HIDP; v = (c2 < HIDN) ? w2[k * HIDN + c2] : 0.f; }
        split_bf16(v, hi[i], lo[i]);
    }
}

__global__ __launch_bounds__(256)
void conv_w3(const float* __restrict__ w3, bf16* __restrict__ hi, bf16* __restrict__ lo)
{
    const size_t n = (size_t)HIDP * DM;
    size_t i = (size_t)blockIdx.x * 256 + threadIdx.x;
    const size_t st = (size_t)gridDim.x * 256;
    for (; i < n; i += st) {
        int r = (int)(i >> 11);
        float v = (r < HIDN) ? w3[i] : 0.f;
        split_bf16(v, hi[i], lo[i]);
    }
}

// ---------------- LayerNorm -> bf16 hi/lo ----------------
__global__ __launch_bounds__(256)
void ln_kernel(const float* __restrict__ x, const float* __restrict__ w,
               const float* __restrict__ b, bf16* __restrict__ ohi,
               bf16* __restrict__ olo)
{
    __shared__ float red[16];
    const int row = blockIdx.x;
    const float* xr = x + (size_t)row * DM;
    float vals[8];
    float s = 0.f, ss = 0.f;
#pragma unroll
    for (int j = 0; j < 8; j++) {
        float v = xr[threadIdx.x + j * 256];
        vals[j] = v; s += v; ss += v * v;
    }
#pragma unroll
    for (int o = 16; o > 0; o >>= 1) {
        s  += __shfl_xor_sync(0xFFFFFFFFu, s,  o);
        ss += __shfl_xor_sync(0xFFFFFFFFu, ss, o);
    }
    const int warp = threadIdx.x >> 5, lane = threadIdx.x & 31;
    if (lane == 0) { red[warp] = s; red[8 + warp] = ss; }
    __syncthreads();
    s = 0.f; ss = 0.f;
#pragma unroll
    for (int k = 0; k < 8; k++) { s += red[k]; ss += red[8 + k]; }
    const float mean = s * (1.f / DM);
    const float var  = ss * (1.f / DM) - mean * mean;
    const float rstd = rsqrtf(var + 1e-5f);
#pragma unroll
    for (int j = 0; j < 8; j++) {
        int col = threadIdx.x + j * 256;
        float o = (vals[j] - mean) * rstd * w[col] + b[col];
        split_bf16(o, ohi[(size_t)row * DM + col], olo[(size_t)row * DM + col]);
    }
}

// ---------------- fused per-head GroupNorm + silu gate ----------------
__global__ __launch_bounds__(256)
void gn_gate(const float* __restrict__ qkvg, const float* __restrict__ r,
             bf16* __restrict__ hi, bf16* __restrict__ lo)
{
    const int gi = blockIdx.x * 8 + (threadIdx.x >> 5);   // group idx: row*16 + h
    const int lane = threadIdx.x & 31;
    const int row = gi >> 4, h = gi & 15;
    const size_t rbase = (size_t)gi * DH + lane * 4;
    const size_t gbase = (size_t)row * QST + 6144 + h * DH + lane * 4;
    float4 v = *reinterpret_cast<const float4*>(r + rbase);
    float s  = v.x + v.y + v.z + v.w;
    float ss = v.x*v.x + v.y*v.y + v.z*v.z + v.w*v.w;
#pragma unroll
    for (int o = 16; o > 0; o >>= 1) {
        s  += __shfl_xor_sync(0xFFFFFFFFu, s,  o);
        ss += __shfl_xor_sync(0xFFFFFFFFu, ss, o);
    }
    const float mean = s * (1.f / DH);
    const float var  = ss * (1.f / DH) - mean * mean;
    const float rstd = rsqrtf(var + 1e-5f);
    float4 gv = *reinterpret_cast<const float4*>(qkvg + gbase);
    float o0 = (gv.x / (1.f + expf(-gv.x))) * ((v.x - mean) * rstd);
    float o1 = (gv.y / (1.f + expf(-gv.y))) * ((v.y - mean) * rstd);
    float o2 = (gv.z / (1.f + expf(-gv.z))) * ((v.z - mean) * rstd);
    float o3 = (gv.w / (1.f + expf(-gv.w))) * ((v.w - mean) * rstd);
    split_bf16(o0, hi[rbase + 0], lo[rbase + 0]);
    split_bf16(o1, hi[rbase + 1], lo[rbase + 1]);
    split_bf16(o2, hi[rbase + 2], lo[rbase + 2]);
    split_bf16(o3, hi[rbase + 3], lo[rbase + 3]);
}

// ---------------- silu(f1) * f2 from packed f12 ----------------
__global__ __launch_bounds__(256)
void gate_split12(const float* __restrict__ f12, bf16* __restrict__ hi,
                  bf16* __restrict__ lo)
{
    const size_t n = (size_t)BSROWS * HIDP;
    size_t i = (size_t)blockIdx.x * 256 + threadIdx.x;
    const size_t st = (size_t)gridDim.x * 256;
    for (; i < n; i += st) {
        size_t row = i / HIDP;
        int col = (int)(i - row * HIDP);
        float a = f12[row * FST + col];
        float bv = f12[row * FST + HIDP + col];
        float v = (a / (1.f + expf(-a))) * bv;
        split_bf16(v, hi[i], lo[i]);
    }
}

// ---------------- bf16x3 GEMM: 3-stage cp.async, single sync per tile ----------------
// Stage layout: Ah@0 (128x80B) | Al@10240 | Bh@20480 (32x272B) | Bl@29184 ; stage = 37888B
#define STG_B 37888u
#define OFF_AL 10240u
#define OFF_BH 20480u
#define OFF_BL 29184u
#define GEMM_SMEM (3*STG_B)   // 113664

__device__ __forceinline__ void gemm_prefetch(
    const bf16* __restrict__ Ahi, const bf16* __restrict__ Alo,
    const bf16* __restrict__ Bhi, const bf16* __restrict__ Blo,
    unsigned st, int bm, int bn, int k0, int K, int N, int tid)
{
#pragma unroll
    for (int i = 0; i < 2; i++) {
        int c = tid + i * 256;
        int row = c >> 2, chn = c & 3;
        size_t go = (size_t)(bm + row) * K + k0 + chn * 8;
        unsigned so = row * 80u + chn * 16u;
        cpa16(st + so, Ahi + go);
        cpa16(st + OFF_AL + so, Alo + go);
    }
#pragma unroll
    for (int i = 0; i < 2; i++) {
        int c = tid + i * 256;
        int row = c >> 4, chn = c & 15;
        size_t go = (size_t)(k0 + row) * N + bn + chn * 8;
        unsigned so = row * 272u + chn * 16u;
        cpa16(st + OFF_BH + so, Bhi + go);
        cpa16(st + OFF_BL + so, Blo + go);
    }
    asm volatile("cp.async.commit_group;\n" ::: "memory");
}

__global__ __launch_bounds__(256, 1)
void gemm_bf16x3(const bf16* __restrict__ Ahi, const bf16* __restrict__ Alo,
                 const bf16* __restrict__ Bhi, const bf16* __restrict__ Blo,
                 const float* __restrict__ Res, float* __restrict__ C,
                 int M, int N, int K)
{
    extern __shared__ __align__(16) char smemraw[];
    const unsigned s0 = (unsigned)__cvta_generic_to_shared(smemraw);

    const int tid  = threadIdx.x;
    const int lane = tid & 31;
    const int warp = tid >> 5;
    const int wm = warp >> 2;
    const int wn = warp & 3;
    const int bm = blockIdx.y * 128;
    const int bn = blockIdx.x * 128;

    const unsigned laneA = (unsigned)(((lane & 7) + ((lane >> 3) & 1) * 8) * 80 + (lane >> 4) * 16);
    const unsigned laneB = (unsigned)(((lane & 7) + ((lane >> 3) & 1) * 8) * 272 + (lane >> 4) * 16);

    float acc[4][4][4];
#pragma unroll
    for (int a = 0; a < 4; a++)
#pragma unroll
        for (int b = 0; b < 4; b++)
#pragma unroll
            for (int c = 0; c < 4; c++) acc[a][b][c] = 0.f;

    const int nk = K >> 5;
    gemm_prefetch(Ahi, Alo, Bhi, Blo, s0,          bm, bn, 0,  K, N, tid);
    gemm_prefetch(Ahi, Alo, Bhi, Blo, s0 + STG_B,  bm, bn, 32, K, N, tid);

    unsigned stage = 0;  // rotating stage base offset: 0, STG_B, 2*STG_B
    for (int t = 0; t < nk; t++) {
        if (t + 1 < nk) asm volatile("cp.async.wait_group 1;\n" ::: "memory");
        else            asm volatile("cp.async.wait_group 0;\n" ::: "memory");
        __syncthreads();

        if (t + 2 < nk) {
            unsigned nst = stage + 2u * STG_B;
            if (nst >= 3u * STG_B) nst -= 3u * STG_B;
            gemm_prefetch(Ahi, Alo, Bhi, Blo, s0 + nst, bm, bn, (t + 2) * 32, K, N, tid);
        }

        const unsigned st = s0 + stage;
        const unsigned aBase = st + (unsigned)(wm * 64 * 80) + laneA;
        const unsigned bBase = st + OFF_BH + (unsigned)(wn * 32 * 2) + laneB;

#pragma unroll
        for (int ks = 0; ks < 2; ks++) {
            unsigned ah[4][4], al[4][4], bh[2][4], bl[2][4];
#pragma unroll
            for (int mt = 0; mt < 4; mt++) {
                unsigned ad = aBase + (unsigned)(mt * 16 * 80 + ks * 32);
                ldsm4(ah[mt], ad);
                ldsm4(al[mt], ad + OFF_AL);
            }
#pragma unroll
            for (int p = 0; p < 2; p++) {
                unsigned bd = bBase + (unsigned)(ks * 16 * 272 + p * 32);
                ldsm4t(bh[p], bd);
                ldsm4t(bl[p], bd + (OFF_BL - OFF_BH));
            }
#pragma unroll
            for (int mt = 0; mt < 4; mt++)
#pragma unroll
                for (int p = 0; p < 2; p++) {
                    mma16(acc[mt][2*p],   ah[mt], bh[p]);
                    mma16(acc[mt][2*p],   ah[mt], bl[p]);
                    mma16(acc[mt][2*p],   al[mt], bh[p]);
                    mma16(acc[mt][2*p+1], ah[mt], bh[p] + 2);
                    mma16(acc[mt][2*p+1], ah[mt], bl[p] + 2);
                    mma16(acc[mt][2*p+1], al[mt], bh[p] + 2);
                }
        }
        stage += STG_B;
        if (stage >= 3u * STG_B) stage = 0;
    }

#pragma unroll
    for (int mt = 0; mt < 4; mt++)
#pragma unroll
        for (int nt = 0; nt < 4; nt++) {
            int r0 = bm + wm * 64 + mt * 16 + (lane >> 2);
            int c0 = bn + wn * 32 + nt * 8 + (lane & 3) * 2;
#pragma unroll
            for (int half = 0; half < 2; half++) {
                int r = r0 + half * 8;
                float2 v = make_float2(acc[mt][nt][half * 2], acc[mt][nt][half * 2 + 1]);
                if (Res) {
                    float2 rv = *reinterpret_cast<const float2*>(&Res[(size_t)r * N + c0]);
                    v.x += rv.x; v.y += rv.y;
                }
                *reinterpret_cast<float2*>(&C[(size_t)r * N + c0]) = v;
            }
        }
}

// ================= chunkwise retention (reads from packed qkvg, stride QST) =====
#define RC_SMEM ((128*68 + 64*136)*4)

__global__ __launch_bounds__(256, 1)
void ret_contrib(const float* __restrict__ K, const float* __restrict__ V,
                 float* __restrict__ CS)
{
    extern __shared__ float smc[];
    float* KsT = smc;              // [128 dh][68]
    float* Vs  = KsT + 128 * 68;   // [64 t][136]

    const int tid  = threadIdx.x;
    const int lane = tid & 31;
    const int warp = tid >> 5;
    const int gq = lane >> 2;
    const int tg = lane & 3;
    const int wm = warp >> 2;
    const int wn = warp & 3;
    const int chunk = blockIdx.x;
    const int bh = blockIdx.y;
    const int b = bh >> 4, h = bh & 15;
    const int kb = chunk * 64;

    const float gamma = 1.f - exp2f(-5.f - (float)h);
    const float lg = log2f(gamma);
    const size_t rowbase = (size_t)(b * SL) * QST + (size_t)h * DH;

#pragma unroll
    for (int it = 0; it < 32; it++) {
        int idx = tid + it * 256;
        int t = idx >> 7, d = idx & 127;
        size_t gidx = rowbase + (size_t)(kb + t) * QST + d;
        float w = 0.08838834764831845f * exp2f((float)(63 - t) * lg);
        KsT[d * 68 + t] = __uint_as_float(f2tf(w * K[gidx]));
        Vs[t * 136 + d] = __uint_as_float(f2tf(V[gidx]));
    }
    __syncthreads();

    float acc[4][4][4];
#pragma unroll
    for (int a = 0; a < 4; a++)
#pragma unroll
        for (int bq = 0; bq < 4; bq++)
#pragma unroll
            for (int c = 0; c < 4; c++) acc[a][bq][c] = 0.f;

#pragma unroll
    for (int ks = 0; ks < 8; ks++) {
        const int kkk = ks * 8;
        unsigned af[4][4], bf[4][2];
#pragma unroll
        for (int mt = 0; mt < 4; mt++) {
            int m = wm * 64 + mt * 16 + gq;
            af[mt][0] = __float_as_uint(KsT[m * 68 + kkk + tg]);
            af[mt][1] = __float_as_uint(KsT[(m + 8) * 68 + kkk + tg]);
            af[mt][2] = __float_as_uint(KsT[m * 68 + kkk + tg + 4]);
            af[mt][3] = __float_as_uint(KsT[(m + 8) * 68 + kkk + tg + 4]);
        }
#pragma unroll
        for (int nt = 0; nt < 4; nt++) {
            int n = wn * 32 + nt * 8 + gq;
            bf[nt][0] = __float_as_uint(Vs[(kkk + tg) * 136 + n]);
            bf[nt][1] = __float_as_uint(Vs[(kkk + tg + 4) * 136 + n]);
        }
#pragma unroll
        for (int mt = 0; mt < 4; mt++)
#pragma unroll
            for (int nt = 0; nt < 4; nt++)
                mma8(acc[mt][nt], af[mt], bf[nt]);
    }

    float* outp = CS + ((size_t)bh * NCH + chunk) * (DH * DH);
#pragma unroll
    for (int mt = 0; mt < 4; mt++)
#pragma unroll
        for (int nt = 0; nt < 4; nt++) {
            int r0 = wm * 64 + mt * 16 + gq;
            int c0 = wn * 32 + nt * 8 + tg * 2;
#pragma unroll
            for (int e = 0; e < 4; e++) {
                int r = r0 + (e >> 1) * 8;
                int c = c0 + (e & 1);
                outp[r * DH + c] = acc[mt][nt][e];
            }
        }
}

__global__ __launch_bounds__(512)
void ret_scan(float* __restrict__ CS)
{
    const int bh = blockIdx.x;
    const int h = bh & 15;
    const float gamma = 1.f - exp2f(-5.f - (float)h);
    const float dec = exp2f(64.f * log2f(gamma));
    float* base = CS + (size_t)bh * NCH * (DH * DH);
    const int tid = threadIdx.x;

    float s[32];
#pragma unroll
    for (int j = 0; j < 32; j++) s[j] = 0.f;
    for (int i = 0; i < NCH; i++) {
        float* p = base + (size_t)i * (DH * DH);
#pragma unroll
        for (int j = 0; j < 32; j++) {
            int e = tid + j * 512;
            float c = p[e];
            p[e] = s[j];
            s[j] = s[j] * dec + c;
        }
    }
}

#define RO_SMEM ((64*132*2 + 64*136 + 64*68 + 128*136 + 128 + 64)*4)

__global__ __launch_bounds__(256, 1)
void ret_out(const float* __restrict__ Q, const float* __restrict__ Kt,
             const float* __restrict__ V, const float* __restrict__ CS,
             float* __restrict__ O)
{
    extern __shared__ float smr[];
    float* Qs  = smr;               // [64][132]
    float* Ks  = Qs + 64 * 132;     // [64][132]
    float* Vs  = Ks + 64 * 132;     // [64][136]
    float* Ss  = Vs + 64 * 136;     // [64][68]
    float* Sts = Ss + 64 * 68;      // [128][136]
    float* dp  = Sts + 128 * 136;   // [128]
    float* dp2 = dp + 128;          // [64]

    const int tid  = threadIdx.x;
    const int lane = tid & 31;
    const int warp = tid >> 5;
    const int gq = lane >> 2;
    const int tg = lane & 3;
    const int wm = warp >> 2;
    const int wn = warp & 3;
    const int chunk = blockIdx.x;
    const int bh = blockIdx.y;
    const int b = bh >> 4, h = bh & 15;
    const int qb = chunk * 64;

    const float gamma = 1.f - exp2f(-5.f - (float)h);
    const float lg = log2f(gamma);
    const size_t rowbase = (size_t)(b * SL) * QST + (size_t)h * DH;
    const size_t obase   = (size_t)(b * SL) * DM  + (size_t)h * DH;
    const float* stp = CS + ((size_t)bh * NCH + chunk) * (DH * DH);

#pragma unroll
    for (int it = 0; it < 32; it++) {
        int idx = tid + it * 256;
        int r = idx >> 7, d = idx & 127;
        size_t gidx = rowbase + (size_t)(qb + r) * QST + d;
        Qs[r * 132 + d] = __uint_as_float(f2tf(Q[gidx]));
        Ks[r * 132 + d] = __uint_as_float(f2tf(Kt[gidx]));
        Vs[r * 136 + d] = __uint_as_float(f2tf(V[gidx]));
    }
#pragma unroll
    for (int it = 0; it < 64; it++) {
        int idx = tid + it * 256;
        int r = idx >> 7, d = idx & 127;
        Sts[r * 136 + d] = __uint_as_float(f2tf(stp[idx]));
    }
    if (tid < 128) {
        int e = tid - 63;
        dp[tid] = (e < 0) ? 0.f : 0.08838834764831845f * exp2f((float)e * lg);
    }
    if (tid < 64) dp2[tid] = exp2f((float)(tid + 1) * lg);
    __syncthreads();

    float acco[2][4][4];
#pragma unroll
    for (int a = 0; a < 2; a++)
#pragma unroll
        for (int bq = 0; bq < 4; bq++)
#pragma unroll
            for (int c = 0; c < 4; c++) acco[a][bq][c] = 0.f;

#pragma unroll
    for (int ks = 0; ks < 16; ks++) {
        const int kkk = ks * 8;
        unsigned af[2][4], bf[4][2];
#pragma unroll
        for (int mt = 0; mt < 2; mt++) {
            int m = wm * 32 + mt * 16 + gq;
            af[mt][0] = __float_as_uint(Qs[m * 132 + kkk + tg]);
            af[mt][1] = __float_as_uint(Qs[(m + 8) * 132 + kkk + tg]);
            af[mt][2] = __float_as_uint(Qs[m * 132 + kkk + tg + 4]);
            af[mt][3] = __float_as_uint(Qs[(m + 8) * 132 + kkk + tg + 4]);
        }
#pragma unroll
        for (int nt = 0; nt < 4; nt++) {
            int n = wn * 32 + nt * 8 + gq;
            bf[nt][0] = __float_as_uint(Sts[(kkk + tg) * 136 + n]);
            bf[nt][1] = __float_as_uint(Sts[(kkk + tg + 4) * 136 + n]);
        }
#pragma unroll
        for (int mt = 0; mt < 2; mt++)
#pragma unroll
            for (int nt = 0; nt < 4; nt++)
                mma8(acco[mt][nt], af[mt], bf[nt]);
    }
#pragma unroll
    for (int mt = 0; mt < 2; mt++) {
        int r0 = wm * 32 + mt * 16 + gq;
        float sc0 = dp2[r0], sc1 = dp2[r0 + 8];
#pragma unroll
        for (int nt = 0; nt < 4; nt++) {
            acco[mt][nt][0] *= sc0; acco[mt][nt][1] *= sc0;
            acco[mt][nt][2] *= sc1; acco[mt][nt][3] *= sc1;
        }
    }

    float accs[2][2][4];
#pragma unroll
    for (int a = 0; a < 2; a++)
#pragma unroll
        for (int bq = 0; bq < 2; bq++)
#pragma unroll
            for (int c = 0; c < 4; c++) accs[a][bq][c] = 0.f;
#pragma unroll
    for (int ks = 0; ks < 16; ks++) {
        const int kkk = ks * 8;
        unsigned af[2][4], bf[2][2];
#pragma unroll
        for (int mt = 0; mt < 2; mt++) {
            int m = wm * 32 + mt * 16 + gq;
            af[mt][0] = __float_as_uint(Qs[m * 132 + kkk + tg]);
            af[mt][1] = __float_as_uint(Qs[(m + 8) * 132 + kkk + tg]);
            af[mt][2] = __float_as_uint(Qs[m * 132 + kkk + tg + 4]);
            af[mt][3] = __float_as_uint(Qs[(m + 8) * 132 + kkk + tg + 4]);
        }
#pragma unroll
        for (int nt = 0; nt < 2; nt++) {
            int n = wn * 16 + nt * 8 + gq;
            bf[nt][0] = __float_as_uint(Ks[n * 132 + kkk + tg]);
            bf[nt][1] = __float_as_uint(Ks[n * 132 + kkk + tg + 4]);
        }
#pragma unroll
        for (int mt = 0; mt < 2; mt++)
#pragma unroll
            for (int nt = 0; nt < 2; nt++)
                mma8(accs[mt][nt], af[mt], bf[nt]);
    }
#pragma unroll
    for (int mt = 0; mt < 2; mt++)
#pragma unroll
        for (int nt = 0; nt < 2; nt++) {
            int sr0 = wm * 32 + mt * 16 + gq;
            int tc0 = wn * 16 + nt * 8 + tg * 2;
#pragma unroll
            for (int e = 0; e < 4; e++) {
                int sr = sr0 + (e >> 1) * 8;
                int tc = tc0 + (e & 1);
                float coeff = dp[sr - tc + 63];
                Ss[sr * 68 + tc] = __uint_as_float(f2tf(accs[mt][nt][e] * coeff));
            }
        }
    __syncthreads();

#pragma unroll
    for (int ks = 0; ks < 8; ks++) {
        const int kkk = ks * 8;
        unsigned af[2][4], bf[4][2];
#pragma unroll
        for (int mt = 0; mt < 2; mt++) {
            int m = wm * 32 + mt * 16 + gq;
            af[mt][0] = __float_as_uint(Ss[m * 68 + kkk + tg]);
            af[mt][1] = __float_as_uint(Ss[(m + 8) * 68 + kkk + tg]);
            af[mt][2] = __float_as_uint(Ss[m * 68 + kkk + tg + 4]);
            af[mt][3] = __float_as_uint(Ss[(m + 8) * 68 + kkk + tg + 4]);
        }
#pragma unroll
        for (int nt = 0; nt < 4; nt++) {
            int n = wn * 32 + nt * 8 + gq;
            bf[nt][0] = __float_as_uint(Vs[(kkk + tg) * 136 + n]);
            bf[nt][1] = __float_as_uint(Vs[(kkk + tg + 4) * 136 + n]);
        }
#pragma unroll
        for (int mt = 0; mt < 2; mt++)
#pragma unroll
            for (int nt = 0; nt < 4; nt++)
                mma8(acco[mt][nt], af[mt], bf[nt]);
    }

#pragma unroll
    for (int mt = 0; mt < 2; mt++)
#pragma unroll
        for (int nt = 0; nt < 4; nt++) {
            int r0 = qb + wm * 32 + mt * 16 + gq;
            int c0 = wn * 32 + nt * 8 + tg * 2;
#pragma unroll
            for (int e = 0; e < 4; e++) {
                int r = r0 + (e >> 1) * 8;
                int c = c0 + (e & 1);
                O[obase + (size_t)r * DM + c] = acco[mt][nt][e];
            }
        }
}

// ---------------- launch ----------------
extern "C" void kernel_launch(void* const* d_in, const int* in_sizes, int n_in,
                              void* d_out, int out_size)
{
    const float* x   = (const float*)d_in[0];
    const float* n1w = (const float*)d_in[1];
    const float* n1b = (const float*)d_in[2];
    const float* wq  = (const float*)d_in[3];
    const float* wk  = (const float*)d_in[4];
    const float* wv  = (const float*)d_in[5];
    const float* wg  = (const float*)d_in[6];
    const float* wo  = (const float*)d_in[7];
    const float* n2w = (const float*)d_in[8];
    const float* n2b = (const float*)d_in[9];
    const float* w1  = (const float*)d_in[10];
    const float* w2  = (const float*)d_in[11];
    const float* w3  = (const float*)d_in[12];
    float* out = (float*)d_out;

    float *qkvg, *r, *x1, *f12, *cs;
    bf16 *h_hi, *h_lo, *h2_hi, *h2_lo, *a_hi, *a_lo, *fg_hi, *fg_lo;
    bf16 *wp_hi, *wp_lo, *wo_hi, *wo_lo, *w12_hi, *w12_lo, *w3_hi, *w3_lo;

    cudaGetSymbolAddress((void**)&qkvg, g_qkvg);
    cudaGetSymbolAddress((void**)&r,    g_r);
    cudaGetSymbolAddress((void**)&x1,   g_x1);
    cudaGetSymbolAddress((void**)&f12,  g_f12);
    cudaGetSymbolAddress((void**)&cs,   g_st);
    cudaGetSymbolAddress((void**)&h_hi,  g_h_hi);
    cudaGetSymbolAddress((void**)&h_lo,  g_h_lo);
    cudaGetSymbolAddress((void**)&h2_hi, g_h2_hi);
    cudaGetSymbolAddress((void**)&h2_lo, g_h2_lo);
    cudaGetSymbolAddress((void**)&a_hi,  g_a_hi);
    cudaGetSymbolAddress((void**)&a_lo,  g_a_lo);
    cudaGetSymbolAddress((void**)&fg_hi, g_fg_hi);
    cudaGetSymbolAddress((void**)&fg_lo, g_fg_lo);
    cudaGetSymbolAddress((void**)&wp_hi,  g_wqkvg_hi); cudaGetSymbolAddress((void**)&wp_lo,  g_wqkvg_lo);
    cudaGetSymbolAddress((void**)&wo_hi,  g_wo_hi);    cudaGetSymbolAddress((void**)&wo_lo,  g_wo_lo);
    cudaGetSymbolAddress((void**)&w12_hi, g_w12_hi);   cudaGetSymbolAddress((void**)&w12_lo, g_w12_lo);
    cudaGetSymbolAddress((void**)&w3_hi,  g_w3_hi);    cudaGetSymbolAddress((void**)&w3_lo,  g_w3_lo);

    cudaFuncSetAttribute((const void*)gemm_bf16x3,
                         cudaFuncAttributeMaxDynamicSharedMemorySize, GEMM_SMEM);
    cudaFuncSetAttribute((const void*)ret_contrib,
                         cudaFuncAttributeMaxDynamicSharedMemorySize, RC_SMEM);
    cudaFuncSetAttribute((const void*)ret_out,
                         cudaFuncAttributeMaxDynamicSharedMemorySize, RO_SMEM);

    // weight packing (4 launches; keeps gemm at ncu -s 5 position)
    conv_qkvg<<<4096, 256>>>(wq, wk, wv, wg, wp_hi, wp_lo);   // 1
    conv_wo<<<2048, 256>>>(wo, wo_hi, wo_lo);                 // 2
    conv_w12<<<4096, 256>>>(w1, w2, w12_hi, w12_lo);          // 3
    conv_w3<<<2048, 256>>>(w3, w3_hi, w3_lo);                 // 4

    ln_kernel<<<BSROWS, 256>>>(x, n1w, n1b, h_hi, h_lo);      // 5

    // 6: merged qkvg projection GEMM — ncu captures this
    gemm_bf16x3<<<dim3(QST / 128, BSROWS / 128), 256, GEMM_SMEM>>>(
        h_hi, h_lo, wp_hi, wp_lo, nullptr, qkvg, BSROWS, QST, DM);

    // chunkwise retention
    ret_contrib<<<dim3(NCH, NB * NH), 256, RC_SMEM>>>(qkvg + 2048, qkvg + 4096, cs);
    ret_scan<<<NB * NH, 512>>>(cs);
    ret_out<<<dim3(NCH, NB * NH), 256, RO_SMEM>>>(qkvg, qkvg + 2048, qkvg + 4096, cs, r);

    gn_gate<<<(BSROWS * NH) / 8, 256>>>(qkvg, r, a_hi, a_lo);
    gemm_bf16x3<<<dim3(DM / 128, BSROWS / 128), 256, GEMM_SMEM>>>(
        a_hi, a_lo, wo_hi, wo_lo, x, x1, BSROWS, DM, DM);

    ln_kernel<<<BSROWS, 256>>>(x1, n2w, n2b, h2_hi, h2_lo);
    gemm_bf16x3<<<dim3(FST / 128, BSROWS / 128), 256, GEMM_SMEM>>>(
        h2_hi, h2_lo, w12_hi, w12_lo, nullptr, f12, BSROWS, FST, DM);
    gate_split12<<<8192, 256>>>(f12, fg_hi, fg_lo);
    gemm_bf16x3<<<dim3(DM / 128, BSROWS / 128), 256, GEMM_SMEM>>>(
        fg_hi, fg_lo, w3_hi, w3_lo, x1, out, BSROWS, DM, HIDP);
}

// round 6
// speedup vs baseline: 2.8207x; 1.0895x over previous
#include <cuda_runtime.h>
#include <cuda_bf16.h>
#include <cstdint>
#include <cstddef>

#define NB 2
#define SL 2048
#define DM 2048
#define NH 16
#define DH 128
#define HIDN 5461
#define HIDP 5504           // padded to multiple of 128
#define BSROWS (NB*SL)      // 4096
#define NCH 32              // chunks per sequence (chunk = 64 rows)
#define QST 8192            // packed qkvg row stride
#define FST 11008           // packed f1|f2 row stride

typedef __nv_bfloat16 bf16;

// ---------------- scratch (device globals: allocation-free rule) ----------------
__device__ float g_qkvg[(size_t)BSROWS*QST];      // q|k|v|g packed
__device__ float g_r [(size_t)BSROWS*DM];
__device__ float g_x1[(size_t)BSROWS*DM];
__device__ float g_f12[(size_t)BSROWS*FST];       // f1|f2 packed
__device__ float g_st[(size_t)NB*NH*NCH*DH*DH];   // chunk states

__device__ __align__(16) bf16 g_h_hi [(size_t)BSROWS*DM];
__device__ __align__(16) bf16 g_h_lo [(size_t)BSROWS*DM];
__device__ __align__(16) bf16 g_h2_hi[(size_t)BSROWS*DM];
__device__ __align__(16) bf16 g_h2_lo[(size_t)BSROWS*DM];
__device__ __align__(16) bf16 g_a_hi [(size_t)BSROWS*DM];
__device__ __align__(16) bf16 g_a_lo [(size_t)BSROWS*DM];
__device__ __align__(16) bf16 g_fg_hi[(size_t)BSROWS*HIDP];
__device__ __align__(16) bf16 g_fg_lo[(size_t)BSROWS*HIDP];

__device__ __align__(16) bf16 g_wqkvg_hi[(size_t)DM*QST], g_wqkvg_lo[(size_t)DM*QST];
__device__ __align__(16) bf16 g_wo_hi[(size_t)DM*DM],  g_wo_lo[(size_t)DM*DM];
__device__ __align__(16) bf16 g_w12_hi[(size_t)DM*FST], g_w12_lo[(size_t)DM*FST];
__device__ __align__(16) bf16 g_w3_hi[(size_t)HIDP*DM], g_w3_lo[(size_t)HIDP*DM];

// ---------------- helpers ----------------
__device__ __forceinline__ unsigned f2tf(float x) {
    unsigned r;
    asm("cvt.rna.tf32.f32 %0, %1;" : "=r"(r) : "f"(x));
    return r;
}

__device__ __forceinline__ void split_bf16(float x, bf16& hi, bf16& lo) {
    hi = __float2bfloat16(x);
    lo = __float2bfloat16(x - __bfloat162float(hi));
}

// split 8 consecutive floats -> 16B hi + 16B lo stores
__device__ __forceinline__ void split8_store(const float* v, bf16* hip, bf16* lop) {
    bf16 hh[8], ll[8];
#pragma unroll
    for (int j = 0; j < 8; j++) split_bf16(v[j], hh[j], ll[j]);
    *reinterpret_cast<uint4*>(hip) = *reinterpret_cast<uint4*>(hh);
    *reinterpret_cast<uint4*>(lop) = *reinterpret_cast<uint4*>(ll);
}

__device__ __forceinline__ void mma8(float* c, const unsigned* a, const unsigned* b) {
    asm volatile(
        "mma.sync.aligned.m16n8k8.row.col.f32.tf32.tf32.f32 "
        "{%0,%1,%2,%3}, {%4,%5,%6,%7}, {%8,%9}, {%0,%1,%2,%3};\n"
        : "+f"(c[0]), "+f"(c[1]), "+f"(c[2]), "+f"(c[3])
        : "r"(a[0]), "r"(a[1]), "r"(a[2]), "r"(a[3]), "r"(b[0]), "r"(b[1]));
}

__device__ __forceinline__ void mma16(float* c, const unsigned* a, const unsigned* b) {
    asm volatile(
        "mma.sync.aligned.m16n8k16.row.col.f32.bf16.bf16.f32 "
        "{%0,%1,%2,%3}, {%4,%5,%6,%7}, {%8,%9}, {%0,%1,%2,%3};\n"
        : "+f"(c[0]), "+f"(c[1]), "+f"(c[2]), "+f"(c[3])
        : "r"(a[0]), "r"(a[1]), "r"(a[2]), "r"(a[3]), "r"(b[0]), "r"(b[1]));
}

__device__ __forceinline__ void ldsm4(unsigned* r, unsigned addr) {
    asm volatile("ldmatrix.sync.aligned.m8n8.x4.shared.b16 {%0,%1,%2,%3}, [%4];\n"
        : "=r"(r[0]), "=r"(r[1]), "=r"(r[2]), "=r"(r[3]) : "r"(addr));
}
__device__ __forceinline__ void ldsm4t(unsigned* r, unsigned addr) {
    asm volatile("ldmatrix.sync.aligned.m8n8.x4.trans.shared.b16 {%0,%1,%2,%3}, [%4];\n"
        : "=r"(r[0]), "=r"(r[1]), "=r"(r[2]), "=r"(r[3]) : "r"(addr));
}
__device__ __forceinline__ void cpa16(unsigned dst, const void* src) {
    asm volatile("cp.async.cg.shared.global [%0], [%1], 16;\n" :: "r"(dst), "l"(src));
}

// ---------------- weight packers (8 elems / thread) ----------------
__global__ __launch_bounds__(256)
void conv_qkvg(const float* __restrict__ wq, const float* __restrict__ wk,
               const float* __restrict__ wv, const float* __restrict__ wg,
               bf16* __restrict__ hi, bf16* __restrict__ lo)
{
    const size_t n8 = (size_t)DM * QST / 8;
    size_t i = (size_t)blockIdx.x * 256 + threadIdx.x;
    const size_t st = (size_t)gridDim.x * 256;
    for (; i < n8; i += st) {
        size_t i8 = i * 8;
        size_t k = i8 >> 13;
        int c = (int)(i8 & (QST - 1));
        int proj = c >> 11, col = c & 2047;
        const float* s = (proj == 0) ? wq : (proj == 1) ? wk : (proj == 2) ? wv : wg;
        float v[8];
        *reinterpret_cast<float4*>(v)     = *reinterpret_cast<const float4*>(s + k * DM + col);
        *reinterpret_cast<float4*>(v + 4) = *reinterpret_cast<const float4*>(s + k * DM + col + 4);
        split8_store(v, hi + i8, lo + i8);
    }
}

__global__ __launch_bounds__(256)
void conv_wo(const float* __restrict__ src, bf16* __restrict__ hi, bf16* __restrict__ lo)
{
    const size_t n8 = (size_t)DM * DM / 8;
    size_t i = (size_t)blockIdx.x * 256 + threadIdx.x;
    const size_t st = (size_t)gridDim.x * 256;
    for (; i < n8; i += st) {
        size_t i8 = i * 8;
        float v[8];
        *reinterpret_cast<float4*>(v)     = *reinterpret_cast<const float4*>(src + i8);
        *reinterpret_cast<float4*>(v + 4) = *reinterpret_cast<const float4*>(src + i8 + 4);
        split8_store(v, hi + i8, lo + i8);
    }
}

__global__ __launch_bounds__(256)
void conv_w12(const float* __restrict__ w1, const float* __restrict__ w2,
              bf16* __restrict__ hi, bf16* __restrict__ lo)
{
    const size_t n8 = (size_t)DM * FST / 8;
    size_t i = (size_t)blockIdx.x * 256 + threadIdx.x;
    const size_t st = (size_t)gridDim.x * 256;
    for (; i < n8; i += st) {
        size_t i8 = i * 8;
        size_t k = i8 / FST;
        int c = (int)(i8 - k * FST);
        const float* w; int cb;
        if (c < HIDP) { w = w1; cb = c; } else { w = w2; cb = c - HIDP; }
        float v[8];
#pragma unroll
        for (int j = 0; j < 8; j++) {
            int col = cb + j;
            v[j] = (col < HIDN) ? w[k * HIDN + col] : 0.f;
        }
        split8_store(v, hi + i8, lo + i8);
    }
}

__global__ __launch_bounds__(256)
void conv_w3(const float* __restrict__ w3, bf16* __restrict__ hi, bf16* __restrict__ lo)
{
    const size_t n8 = (size_t)HIDP * DM / 8;
    size_t i = (size_t)blockIdx.x * 256 + threadIdx.x;
    const size_t st = (size_t)gridDim.x * 256;
    for (; i < n8; i += st) {
        size_t i8 = i * 8;
        int r = (int)(i8 >> 11);
        float v[8];
        if (r < HIDN) {
            *reinterpret_cast<float4*>(v)     = *reinterpret_cast<const float4*>(w3 + i8);
            *reinterpret_cast<float4*>(v + 4) = *reinterpret_cast<const float4*>(w3 + i8 + 4);
        } else {
#pragma unroll
            for (int j = 0; j < 8; j++) v[j] = 0.f;
        }
        split8_store(v, hi + i8, lo + i8);
    }
}

// ---------------- LayerNorm -> bf16 hi/lo ----------------
__global__ __launch_bounds__(256)
void ln_kernel(const float* __restrict__ x, const float* __restrict__ w,
               const float* __restrict__ b, bf16* __restrict__ ohi,
               bf16* __restrict__ olo)
{
    __shared__ float red[16];
    const int row = blockIdx.x;
    const float* xr = x + (size_t)row * DM;
    float vals[8];
    float s = 0.f, ss = 0.f;
#pragma unroll
    for (int j = 0; j < 8; j++) {
        float v = xr[threadIdx.x + j * 256];
        vals[j] = v; s += v; ss += v * v;
    }
#pragma unroll
    for (int o = 16; o > 0; o >>= 1) {
        s  += __shfl_xor_sync(0xFFFFFFFFu, s,  o);
        ss += __shfl_xor_sync(0xFFFFFFFFu, ss, o);
    }
    const int warp = threadIdx.x >> 5, lane = threadIdx.x & 31;
    if (lane == 0) { red[warp] = s; red[8 + warp] = ss; }
    __syncthreads();
    s = 0.f; ss = 0.f;
#pragma unroll
    for (int k = 0; k < 8; k++) { s += red[k]; ss += red[8 + k]; }
    const float mean = s * (1.f / DM);
    const float var  = ss * (1.f / DM) - mean * mean;
    const float rstd = rsqrtf(var + 1e-5f);
#pragma unroll
    for (int j = 0; j < 8; j++) {
        int col = threadIdx.x + j * 256;
        float o = (vals[j] - mean) * rstd * w[col] + b[col];
        split_bf16(o, ohi[(size_t)row * DM + col], olo[(size_t)row * DM + col]);
    }
}

// ---------------- fused per-head GroupNorm + silu gate ----------------
__global__ __launch_bounds__(256)
void gn_gate(const float* __restrict__ qkvg, const float* __restrict__ r,
             bf16* __restrict__ hi, bf16* __restrict__ lo)
{
    const int gi = blockIdx.x * 8 + (threadIdx.x >> 5);   // group idx: row*16 + h
    const int lane = threadIdx.x & 31;
    const int row = gi >> 4, h = gi & 15;
    const size_t rbase = (size_t)gi * DH + lane * 4;
    const size_t gbase = (size_t)row * QST + 6144 + h * DH + lane * 4;
    float4 v = *reinterpret_cast<const float4*>(r + rbase);
    float s  = v.x + v.y + v.z + v.w;
    float ss = v.x*v.x + v.y*v.y + v.z*v.z + v.w*v.w;
#pragma unroll
    for (int o = 16; o > 0; o >>= 1) {
        s  += __shfl_xor_sync(0xFFFFFFFFu, s,  o);
        ss += __shfl_xor_sync(0xFFFFFFFFu, ss, o);
    }
    const float mean = s * (1.f / DH);
    const float var  = ss * (1.f / DH) - mean * mean;
    const float rstd = rsqrtf(var + 1e-5f);
    float4 gv = *reinterpret_cast<const float4*>(qkvg + gbase);
    float o0 = (gv.x / (1.f + expf(-gv.x))) * ((v.x - mean) * rstd);
    float o1 = (gv.y / (1.f + expf(-gv.y))) * ((v.y - mean) * rstd);
    float o2 = (gv.z / (1.f + expf(-gv.z))) * ((v.z - mean) * rstd);
    float o3 = (gv.w / (1.f + expf(-gv.w))) * ((v.w - mean) * rstd);
    split_bf16(o0, hi[rbase + 0], lo[rbase + 0]);
    split_bf16(o1, hi[rbase + 1], lo[rbase + 1]);
    split_bf16(o2, hi[rbase + 2], lo[rbase + 2]);
    split_bf16(o3, hi[rbase + 3], lo[rbase + 3]);
}

// ---------------- silu(f1) * f2 from packed f12 (8/thread) ----------------
__global__ __launch_bounds__(256)
void gate_split12(const float* __restrict__ f12, bf16* __restrict__ hi,
                  bf16* __restrict__ lo)
{
    const size_t n8 = (size_t)BSROWS * HIDP / 8;
    size_t i = (size_t)blockIdx.x * 256 + threadIdx.x;
    const size_t st = (size_t)gridDim.x * 256;
    for (; i < n8; i += st) {
        size_t i8 = i * 8;
        size_t row = i8 / HIDP;
        int col = (int)(i8 - row * HIDP);
        const float* pa = f12 + row * FST + col;
        const float* pb = pa + HIDP;
        float a[8], bvv[8], v[8];
        *reinterpret_cast<float4*>(a)       = *reinterpret_cast<const float4*>(pa);
        *reinterpret_cast<float4*>(a + 4)   = *reinterpret_cast<const float4*>(pa + 4);
        *reinterpret_cast<float4*>(bvv)     = *reinterpret_cast<const float4*>(pb);
        *reinterpret_cast<float4*>(bvv + 4) = *reinterpret_cast<const float4*>(pb + 4);
#pragma unroll
        for (int j = 0; j < 8; j++)
            v[j] = (a[j] / (1.f + expf(-a[j]))) * bvv[j];
        split8_store(v, hi + i8, lo + i8);
    }
}

// ---------------- bf16x3 GEMM: CTA tile 128x256, 3-stage cp.async ----------------
// Stage: Ah@0 (128x80B=10240) | Al@10240 | Bh@20480 (32x528B=16896) | Bl@37376 ; stage=54272B
#define STG_B 54272u
#define OFF_AL 10240u
#define OFF_BH 20480u
#define OFF_BL 37376u
#define GEMM_SMEM (3*STG_B)   // 162816

__device__ __forceinline__ void gemm_prefetch(
    const bf16* __restrict__ Ahi, const bf16* __restrict__ Alo,
    const bf16* __restrict__ Bhi, const bf16* __restrict__ Blo,
    unsigned st, int bm, int bn, int k0, int K, int N, int tid)
{
#pragma unroll
    for (int i = 0; i < 2; i++) {
        int c = tid + i * 256;
        int row = c >> 2, chn = c & 3;
        size_t go = (size_t)(bm + row) * K + k0 + chn * 8;
        unsigned so = row * 80u + chn * 16u;
        cpa16(st + so, Ahi + go);
        cpa16(st + OFF_AL + so, Alo + go);
    }
#pragma unroll
    for (int i = 0; i < 4; i++) {
        int c = tid + i * 256;
        int row = c >> 5, chn = c & 31;
        size_t go = (size_t)(k0 + row) * N + bn + chn * 8;
        unsigned so = row * 528u + chn * 16u;
        cpa16(st + OFF_BH + so, Bhi + go);
        cpa16(st + OFF_BL + so, Blo + go);
    }
    asm volatile("cp.async.commit_group;\n" ::: "memory");
}

__global__ __launch_bounds__(256, 1)
void gemm_bf16x3(const bf16* __restrict__ Ahi, const bf16* __restrict__ Alo,
                 const bf16* __restrict__ Bhi, const bf16* __restrict__ Blo,
                 const float* __restrict__ Res, float* __restrict__ C,
                 int M, int N, int K)
{
    extern __shared__ __align__(16) char smemraw[];
    const unsigned s0 = (unsigned)__cvta_generic_to_shared(smemraw);

    const int tid  = threadIdx.x;
    const int lane = tid & 31;
    const int warp = tid >> 5;
    const int wm = warp >> 2;     // 0..1 : 64 rows
    const int wn = warp & 3;      // 0..3 : 64 cols
    const int bm = blockIdx.y * 128;
    const int bn = blockIdx.x * 256;

    const unsigned laneA = (unsigned)(((lane & 7) + ((lane >> 3) & 1) * 8) * 80 + (lane >> 4) * 16);
    const unsigned laneB = (unsigned)(((lane & 7) + ((lane >> 3) & 1) * 8) * 528 + (lane >> 4) * 16);

    float acc[4][8][4];
#pragma unroll
    for (int a = 0; a < 4; a++)
#pragma unroll
        for (int b = 0; b < 8; b++)
#pragma unroll
            for (int c = 0; c < 4; c++) acc[a][b][c] = 0.f;

    const int nk = K >> 5;
    gemm_prefetch(Ahi, Alo, Bhi, Blo, s0,          bm, bn, 0,  K, N, tid);
    gemm_prefetch(Ahi, Alo, Bhi, Blo, s0 + STG_B,  bm, bn, 32, K, N, tid);

    unsigned stage = 0;
    for (int t = 0; t < nk; t++) {
        if (t + 1 < nk) asm volatile("cp.async.wait_group 1;\n" ::: "memory");
        else            asm volatile("cp.async.wait_group 0;\n" ::: "memory");
        __syncthreads();

        if (t + 2 < nk) {
            unsigned nst = stage + 2u * STG_B;
            if (nst >= 3u * STG_B) nst -= 3u * STG_B;
            gemm_prefetch(Ahi, Alo, Bhi, Blo, s0 + nst, bm, bn, (t + 2) * 32, K, N, tid);
        }

        const unsigned st = s0 + stage;
        const unsigned aBase = st + (unsigned)(wm * 64 * 80) + laneA;
        const unsigned bBase = st + OFF_BH + (unsigned)(wn * 64 * 2) + laneB;

#pragma unroll
        for (int ks = 0; ks < 2; ks++) {
            unsigned ah[4][4], al[4][4];
#pragma unroll
            for (int mt = 0; mt < 4; mt++) {
                unsigned ad = aBase + (unsigned)(mt * 16 * 80 + ks * 32);
                ldsm4(ah[mt], ad);
                ldsm4(al[mt], ad + OFF_AL);
            }
#pragma unroll
            for (int p = 0; p < 4; p++) {
                unsigned bh[4], bl[4];
                unsigned bd = bBase + (unsigned)(ks * 16 * 528 + p * 32);
                ldsm4t(bh, bd);
                ldsm4t(bl, bd + (OFF_BL - OFF_BH));
#pragma unroll
                for (int mt = 0; mt < 4; mt++) {
                    mma16(acc[mt][2*p],   ah[mt], bh);
                    mma16(acc[mt][2*p],   ah[mt], bl);
                    mma16(acc[mt][2*p],   al[mt], bh);
                    mma16(acc[mt][2*p+1], ah[mt], bh + 2);
                    mma16(acc[mt][2*p+1], ah[mt], bl + 2);
                    mma16(acc[mt][2*p+1], al[mt], bh + 2);
                }
            }
        }
        stage += STG_B;
        if (stage >= 3u * STG_B) stage = 0;
    }

#pragma unroll
    for (int mt = 0; mt < 4; mt++)
#pragma unroll
        for (int nt = 0; nt < 8; nt++) {
            int r0 = bm + wm * 64 + mt * 16 + (lane >> 2);
            int c0 = bn + wn * 64 + nt * 8 + (lane & 3) * 2;
#pragma unroll
            for (int half = 0; half < 2; half++) {
                int r = r0 + half * 8;
                float2 v = make_float2(acc[mt][nt][half * 2], acc[mt][nt][half * 2 + 1]);
                if (Res) {
                    float2 rv = *reinterpret_cast<const float2*>(&Res[(size_t)r * N + c0]);
                    v.x += rv.x; v.y += rv.y;
                }
                *reinterpret_cast<float2*>(&C[(size_t)r * N + c0]) = v;
            }
        }
}

// ================= chunkwise retention (reads from packed qkvg, stride QST) =====
#define RC_SMEM ((128*68 + 64*136)*4)

__global__ __launch_bounds__(256, 1)
void ret_contrib(const float* __restrict__ K, const float* __restrict__ V,
                 float* __restrict__ CS)
{
    extern __shared__ float smc[];
    float* KsT = smc;              // [128 dh][68]
    float* Vs  = KsT + 128 * 68;   // [64 t][136]

    const int tid  = threadIdx.x;
    const int lane = tid & 31;
    const int warp = tid >> 5;
    const int gq = lane >> 2;
    const int tg = lane & 3;
    const int wm = warp >> 2;
    const int wn = warp & 3;
    const int chunk = blockIdx.x;
    const int bh = blockIdx.y;
    const int b = bh >> 4, h = bh & 15;
    const int kb = chunk * 64;

    const float gamma = 1.f - exp2f(-5.f - (float)h);
    const float lg = log2f(gamma);
    const size_t rowbase = (size_t)(b * SL) * QST + (size_t)h * DH;

#pragma unroll
    for (int it = 0; it < 32; it++) {
        int idx = tid + it * 256;
        int t = idx >> 7, d = idx & 127;
        size_t gidx = rowbase + (size_t)(kb + t) * QST + d;
        float w = 0.08838834764831845f * exp2f((float)(63 - t) * lg);
        KsT[d * 68 + t] = __uint_as_float(f2tf(w * K[gidx]));
        Vs[t * 136 + d] = __uint_as_float(f2tf(V[gidx]));
    }
    __syncthreads();

    float acc[4][4][4];
#pragma unroll
    for (int a = 0; a < 4; a++)
#pragma unroll
        for (int bq = 0; bq < 4; bq++)
#pragma unroll
            for (int c = 0; c < 4; c++) acc[a][bq][c] = 0.f;

#pragma unroll
    for (int ks = 0; ks < 8; ks++) {
        const int kkk = ks * 8;
        unsigned af[4][4], bf[4][2];
#pragma unroll
        for (int mt = 0; mt < 4; mt++) {
            int m = wm * 64 + mt * 16 + gq;
            af[mt][0] = __float_as_uint(KsT[m * 68 + kkk + tg]);
            af[mt][1] = __float_as_uint(KsT[(m + 8) * 68 + kkk + tg]);
            af[mt][2] = __float_as_uint(KsT[m * 68 + kkk + tg + 4]);
            af[mt][3] = __float_as_uint(KsT[(m + 8) * 68 + kkk + tg + 4]);
        }
#pragma unroll
        for (int nt = 0; nt < 4; nt++) {
            int n = wn * 32 + nt * 8 + gq;
            bf[nt][0] = __float_as_uint(Vs[(kkk + tg) * 136 + n]);
            bf[nt][1] = __float_as_uint(Vs[(kkk + tg + 4) * 136 + n]);
        }
#pragma unroll
        for (int mt = 0; mt < 4; mt++)
#pragma unroll
            for (int nt = 0; nt < 4; nt++)
                mma8(acc[mt][nt], af[mt], bf[nt]);
    }

    float* outp = CS + ((size_t)bh * NCH + chunk) * (DH * DH);
#pragma unroll
    for (int mt = 0; mt < 4; mt++)
#pragma unroll
        for (int nt = 0; nt < 4; nt++) {
            int r0 = wm * 64 + mt * 16 + gq;
            int c0 = wn * 32 + nt * 8 + tg * 2;
#pragma unroll
            for (int e = 0; e < 4; e++) {
                int r = r0 + (e >> 1) * 8;
                int c = c0 + (e & 1);
                outp[r * DH + c] = acc[mt][nt][e];
            }
        }
}

__global__ __launch_bounds__(512)
void ret_scan(float* __restrict__ CS)
{
    const int bh = blockIdx.x;
    const int h = bh & 15;
    const float gamma = 1.f - exp2f(-5.f - (float)h);
    const float dec = exp2f(64.f * log2f(gamma));
    float* base = CS + (size_t)bh * NCH * (DH * DH);
    const int tid = threadIdx.x;

    float s[32];
#pragma unroll
    for (int j = 0; j < 32; j++) s[j] = 0.f;
    for (int i = 0; i < NCH; i++) {
        float* p = base + (size_t)i * (DH * DH);
#pragma unroll
        for (int j = 0; j < 32; j++) {
            int e = tid + j * 512;
            float c = p[e];
            p[e] = s[j];
            s[j] = s[j] * dec + c;
        }
    }
}

#define RO_SMEM ((64*132*2 + 64*136 + 64*68 + 128*136 + 128 + 64)*4)

__global__ __launch_bounds__(256, 1)
void ret_out(const float* __restrict__ Q, const float* __restrict__ Kt,
             const float* __restrict__ V, const float* __restrict__ CS,
             float* __restrict__ O)
{
    extern __shared__ float smr[];
    float* Qs  = smr;               // [64][132]
    float* Ks  = Qs + 64 * 132;     // [64][132]
    float* Vs  = Ks + 64 * 132;     // [64][136]
    float* Ss  = Vs + 64 * 136;     // [64][68]
    float* Sts = Ss + 64 * 68;      // [128][136]
    float* dp  = Sts + 128 * 136;   // [128]
    float* dp2 = dp + 128;          // [64]

    const int tid  = threadIdx.x;
    const int lane = tid & 31;
    const int warp = tid >> 5;
    const int gq = lane >> 2;
    const int tg = lane & 3;
    const int wm = warp >> 2;
    const int wn = warp & 3;
    const int chunk = blockIdx.x;
    const int bh = blockIdx.y;
    const int b = bh >> 4, h = bh & 15;
    const int qb = chunk * 64;

    const float gamma = 1.f - exp2f(-5.f - (float)h);
    const float lg = log2f(gamma);
    const size_t rowbase = (size_t)(b * SL) * QST + (size_t)h * DH;
    const size_t obase   = (size_t)(b * SL) * DM  + (size_t)h * DH;
    const float* stp = CS + ((size_t)bh * NCH + chunk) * (DH * DH);

#pragma unroll
    for (int it = 0; it < 32; it++) {
        int idx = tid + it * 256;
        int r = idx >> 7, d = idx & 127;
        size_t gidx = rowbase + (size_t)(qb + r) * QST + d;
        Qs[r * 132 + d] = __uint_as_float(f2tf(Q[gidx]));
        Ks[r * 132 + d] = __uint_as_float(f2tf(Kt[gidx]));
        Vs[r * 136 + d] = __uint_as_float(f2tf(V[gidx]));
    }
#pragma unroll
    for (int it = 0; it < 64; it++) {
        int idx = tid + it * 256;
        int r = idx >> 7, d = idx & 127;
        Sts[r * 136 + d] = __uint_as_float(f2tf(stp[idx]));
    }
    if (tid < 128) {
        int e = tid - 63;
        dp[tid] = (e < 0) ? 0.f : 0.08838834764831845f * exp2f((float)e * lg);
    }
    if (tid < 64) dp2[tid] = exp2f((float)(tid + 1) * lg);
    __syncthreads();

    float acco[2][4][4];
#pragma unroll
    for (int a = 0; a < 2; a++)
#pragma unroll
        for (int bq = 0; bq < 4; bq++)
#pragma unroll
            for (int c = 0; c < 4; c++) acco[a][bq][c] = 0.f;

#pragma unroll
    for (int ks = 0; ks < 16; ks++) {
        const int kkk = ks * 8;
        unsigned af[2][4], bf[4][2];
#pragma unroll
        for (int mt = 0; mt < 2; mt++) {
            int m = wm * 32 + mt * 16 + gq;
            af[mt][0] = __float_as_uint(Qs[m * 132 + kkk + tg]);
            af[mt][1] = __float_as_uint(Qs[(m + 8) * 132 + kkk + tg]);
            af[mt][2] = __float_as_uint(Qs[m * 132 + kkk + tg + 4]);
            af[mt][3] = __float_as_uint(Qs[(m + 8) * 132 + kkk + tg + 4]);
        }
#pragma unroll
        for (int nt = 0; nt < 4; nt++) {
            int n = wn * 32 + nt * 8 + gq;
            bf[nt][0] = __float_as_uint(Sts[(kkk + tg) * 136 + n]);
            bf[nt][1] = __float_as_uint(Sts[(kkk + tg + 4) * 136 + n]);
        }
#pragma unroll
        for (int mt = 0; mt < 2; mt++)
#pragma unroll
            for (int nt = 0; nt < 4; nt++)
                mma8(acco[mt][nt], af[mt], bf[nt]);
    }
#pragma unroll
    for (int mt = 0; mt < 2; mt++) {
        int r0 = wm * 32 + mt * 16 + gq;
        float sc0 = dp2[r0], sc1 = dp2[r0 + 8];
#pragma unroll
        for (int nt = 0; nt < 4; nt++) {
            acco[mt][nt][0] *= sc0; acco[mt][nt][1] *= sc0;
            acco[mt][nt][2] *= sc1; acco[mt][nt][3] *= sc1;
        }
    }

    float accs[2][2][4];
#pragma unroll
    for (int a = 0; a < 2; a++)
#pragma unroll
        for (int bq = 0; bq < 2; bq++)
#pragma unroll
            for (int c = 0; c < 4; c++) accs[a][bq][c] = 0.f;
#pragma unroll
    for (int ks = 0; ks < 16; ks++) {
        const int kkk = ks * 8;
        unsigned af[2][4], bf[2][2];
#pragma unroll
        for (int mt = 0; mt < 2; mt++) {
            int m = wm * 32 + mt * 16 + gq;
            af[mt][0] = __float_as_uint(Qs[m * 132 + kkk + tg]);
            af[mt][1] = __float_as_uint(Qs[(m + 8) * 132 + kkk + tg]);
            af[mt][2] = __float_as_uint(Qs[m * 132 + kkk + tg + 4]);
            af[mt][3] = __float_as_uint(Qs[(m + 8) * 132 + kkk + tg + 4]);
        }
#pragma unroll
        for (int nt = 0; nt < 2; nt++) {
            int n = wn * 16 + nt * 8 + gq;
            bf[nt][0] = __float_as_uint(Ks[n * 132 + kkk + tg]);
            bf[nt][1] = __float_as_uint(Ks[n * 132 + kkk + tg + 4]);
        }
#pragma unroll
        for (int mt = 0; mt < 2; mt++)
#pragma unroll
            for (int nt = 0; nt < 2; nt++)
                mma8(accs[mt][nt], af[mt], bf[nt]);
    }
#pragma unroll
    for (int mt = 0; mt < 2; mt++)
#pragma unroll
        for (int nt = 0; nt < 2; nt++) {
            int sr0 = wm * 32 + mt * 16 + gq;
            int tc0 = wn * 16 + nt * 8 + tg * 2;
#pragma unroll
            for (int e = 0; e < 4; e++) {
                int sr = sr0 + (e >> 1) * 8;
                int tc = tc0 + (e & 1);
                float coeff = dp[sr - tc + 63];
                Ss[sr * 68 + tc] = __uint_as_float(f2tf(accs[mt][nt][e] * coeff));
            }
        }
    __syncthreads();

#pragma unroll
    for (int ks = 0; ks < 8; ks++) {
        const int kkk = ks * 8;
        unsigned af[2][4], bf[4][2];
#pragma unroll
        for (int mt = 0; mt < 2; mt++) {
            int m = wm * 32 + mt * 16 + gq;
            af[mt][0] = __float_as_uint(Ss[m * 68 + kkk + tg]);
            af[mt][1] = __float_as_uint(Ss[(m + 8) * 68 + kkk + tg]);
            af[mt][2] = __float_as_uint(Ss[m * 68 + kkk + tg + 4]);
            af[mt][3] = __float_as_uint(Ss[(m + 8) * 68 + kkk + tg + 4]);
        }
#pragma unroll
        for (int nt = 0; nt < 4; nt++) {
            int n = wn * 32 + nt * 8 + gq;
            bf[nt][0] = __float_as_uint(Vs[(kkk + tg) * 136 + n]);
            bf[nt][1] = __float_as_uint(Vs[(kkk + tg + 4) * 136 + n]);
        }
#pragma unroll
        for (int mt = 0; mt < 2; mt++)
#pragma unroll
            for (int nt = 0; nt < 4; nt++)
                mma8(acco[mt][nt], af[mt], bf[nt]);
    }

#pragma unroll
    for (int mt = 0; mt < 2; mt++)
#pragma unroll
        for (int nt = 0; nt < 4; nt++) {
            int r0 = qb + wm * 32 + mt * 16 + gq;
            int c0 = wn * 32 + nt * 8 + tg * 2;
#pragma unroll
            for (int e = 0; e < 4; e++) {
                int r = r0 + (e >> 1) * 8;
                int c = c0 + (e & 1);
                O[obase + (size_t)r * DM + c] = acco[mt][nt][e];
            }
        }
}

// ---------------- launch ----------------
extern "C" void kernel_launch(void* const* d_in, const int* in_sizes, int n_in,
                              void* d_out, int out_size)
{
    const float* x   = (const float*)d_in[0];
    const float* n1w = (const float*)d_in[1];
    const float* n1b = (const float*)d_in[2];
    const float* wq  = (const float*)d_in[3];
    const float* wk  = (const float*)d_in[4];
    const float* wv  = (const float*)d_in[5];
    const float* wg  = (const float*)d_in[6];
    const float* wo  = (const float*)d_in[7];
    const float* n2w = (const float*)d_in[8];
    const float* n2b = (const float*)d_in[9];
    const float* w1  = (const float*)d_in[10];
    const float* w2  = (const float*)d_in[11];
    const float* w3  = (const float*)d_in[12];
    float* out = (float*)d_out;

    float *qkvg, *r, *x1, *f12, *cs;
    bf16 *h_hi, *h_lo, *h2_hi, *h2_lo, *a_hi, *a_lo, *fg_hi, *fg_lo;
    bf16 *wp_hi, *wp_lo, *wo_hi, *wo_lo, *w12_hi, *w12_lo, *w3_hi, *w3_lo;

    cudaGetSymbolAddress((void**)&qkvg, g_qkvg);
    cudaGetSymbolAddress((void**)&r,    g_r);
    cudaGetSymbolAddress((void**)&x1,   g_x1);
    cudaGetSymbolAddress((void**)&f12,  g_f12);
    cudaGetSymbolAddress((void**)&cs,   g_st);
    cudaGetSymbolAddress((void**)&h_hi,  g_h_hi);
    cudaGetSymbolAddress((void**)&h_lo,  g_h_lo);
    cudaGetSymbolAddress((void**)&h2_hi, g_h2_hi);
    cudaGetSymbolAddress((void**)&h2_lo, g_h2_lo);
    cudaGetSymbolAddress((void**)&a_hi,  g_a_hi);
    cudaGetSymbolAddress((void**)&a_lo,  g_a_lo);
    cudaGetSymbolAddress((void**)&fg_hi, g_fg_hi);
    cudaGetSymbolAddress((void**)&fg_lo, g_fg_lo);
    cudaGetSymbolAddress((void**)&wp_hi,  g_wqkvg_hi); cudaGetSymbolAddress((void**)&wp_lo,  g_wqkvg_lo);
    cudaGetSymbolAddress((void**)&wo_hi,  g_wo_hi);    cudaGetSymbolAddress((void**)&wo_lo,  g_wo_lo);
    cudaGetSymbolAddress((void**)&w12_hi, g_w12_hi);   cudaGetSymbolAddress((void**)&w12_lo, g_w12_lo);
    cudaGetSymbolAddress((void**)&w3_hi,  g_w3_hi);    cudaGetSymbolAddress((void**)&w3_lo,  g_w3_lo);

    cudaFuncSetAttribute((const void*)gemm_bf16x3,
                         cudaFuncAttributeMaxDynamicSharedMemorySize, GEMM_SMEM);
    cudaFuncSetAttribute((const void*)ret_contrib,
                         cudaFuncAttributeMaxDynamicSharedMemorySize, RC_SMEM);
    cudaFuncSetAttribute((const void*)ret_out,
                         cudaFuncAttributeMaxDynamicSharedMemorySize, RO_SMEM);

    // weight packing
    conv_qkvg<<<4096, 256>>>(wq, wk, wv, wg, wp_hi, wp_lo);
    conv_wo<<<2048, 256>>>(wo, wo_hi, wo_lo);
    conv_w12<<<4096, 256>>>(w1, w2, w12_hi, w12_lo);
    conv_w3<<<2048, 256>>>(w3, w3_hi, w3_lo);

    ln_kernel<<<BSROWS, 256>>>(x, n1w, n1b, h_hi, h_lo);

    // merged qkvg projection GEMM
    gemm_bf16x3<<<dim3(QST / 256, BSROWS / 128), 256, GEMM_SMEM>>>(
        h_hi, h_lo, wp_hi, wp_lo, nullptr, qkvg, BSROWS, QST, DM);

    // chunkwise retention
    ret_contrib<<<dim3(NCH, NB * NH), 256, RC_SMEM>>>(qkvg + 2048, qkvg + 4096, cs);
    ret_scan<<<NB * NH, 512>>>(cs);
    ret_out<<<dim3(NCH, NB * NH), 256, RO_SMEM>>>(qkvg, qkvg + 2048, qkvg + 4096, cs, r);

    gn_gate<<<(BSROWS * NH) / 8, 256>>>(qkvg, r, a_hi, a_lo);
    gemm_bf16x3<<<dim3(DM / 256, BSROWS / 128), 256, GEMM_SMEM>>>(
        a_hi, a_lo, wo_hi, wo_lo, x, x1, BSROWS, DM, DM);

    ln_kernel<<<BSROWS, 256>>>(x1, n2w, n2b, h2_hi, h2_lo);
    gemm_bf16x3<<<dim3(FST / 256, BSROWS / 128), 256, GEMM_SMEM>>>(
        h2_hi, h2_lo, w12_hi, w12_lo, nullptr, f12, BSROWS, FST, DM);
    gate_split12<<<8192, 256>>>(f12, fg_hi, fg_lo);
    gemm_bf16x3<<<dim3(DM / 256, BSROWS / 128), 256, GEMM_SMEM>>>(
        fg_hi, fg_lo, w3_hi, w3_lo, x1, out, BSROWS, DM, HIDP);
}